// round 1
// baseline (speedup 1.0000x reference)
#include <cuda_runtime.h>
#include <math.h>

#define SLEN 2048
#define HIDDEN 2880
#define NHEADS 64
#define NKV 8
#define HDIM 64
#define QDIM (NHEADS * HDIM)   /* 4096 */
#define KVDIM (NKV * HDIM)     /* 512  */

// -------------------- scratch (static device globals; no allocation) ---------
__device__ float g_q[SLEN * QDIM];    // 32 MB
__device__ float g_k[SLEN * KVDIM];   //  4 MB
__device__ float g_v[SLEN * KVDIM];   //  4 MB
__device__ float g_ao[SLEN * QDIM];   // 32 MB

// ============================================================================
// SGEMM: C[m][n] = sum_k A[m][k] * W[n][k] + bias[n]
// A: [M, K] row-major, W: [N, K] row-major (both K-contiguous).
// 128x128 tile, BK=8, 256 threads, 8x8 microtile per thread.
// M is always a multiple of 128 here; N may not be (guarded). K % 8 == 0.
// ============================================================================
__global__ __launch_bounds__(256) void sgemm_bias(
    const float* __restrict__ A, const float* __restrict__ W,
    const float* __restrict__ bias, float* __restrict__ C,
    int M, int N, int Kdim)
{
    __shared__ float As[8][128];
    __shared__ float Bs[8][128];

    const int tid = threadIdx.x;
    const int m0 = blockIdx.y * 128;
    const int n0 = blockIdx.x * 128;
    const int lr = tid >> 1;          // 0..127 : row within tile for loads
    const int lk = (tid & 1) * 4;     // 0 or 4 : k offset for loads
    const int ty = tid >> 4;          // 0..15
    const int tx = tid & 15;          // 0..15

    float acc[8][8];
#pragma unroll
    for (int i = 0; i < 8; i++)
#pragma unroll
        for (int j = 0; j < 8; j++) acc[i][j] = 0.0f;

    const int wn = n0 + lr;
    const bool wok = (wn < N);
    const float* Aptr = A + (size_t)(m0 + lr) * Kdim + lk;
    const float* Wptr = W + (size_t)(wok ? wn : 0) * Kdim + lk;

    for (int k0 = 0; k0 < Kdim; k0 += 8) {
        float4 av = *(const float4*)(Aptr + k0);
        float4 bv = make_float4(0.f, 0.f, 0.f, 0.f);
        if (wok) bv = *(const float4*)(Wptr + k0);

        __syncthreads();  // previous iteration's reads complete
        As[lk + 0][lr] = av.x; As[lk + 1][lr] = av.y;
        As[lk + 2][lr] = av.z; As[lk + 3][lr] = av.w;
        Bs[lk + 0][lr] = bv.x; Bs[lk + 1][lr] = bv.y;
        Bs[lk + 2][lr] = bv.z; Bs[lk + 3][lr] = bv.w;
        __syncthreads();

#pragma unroll
        for (int kk = 0; kk < 8; kk++) {
            float a[8], b[8];
            *(float4*)&a[0] = *(const float4*)&As[kk][ty * 8];
            *(float4*)&a[4] = *(const float4*)&As[kk][ty * 8 + 4];
            *(float4*)&b[0] = *(const float4*)&Bs[kk][tx * 8];
            *(float4*)&b[4] = *(const float4*)&Bs[kk][tx * 8 + 4];
#pragma unroll
            for (int i = 0; i < 8; i++)
#pragma unroll
                for (int j = 0; j < 8; j++)
                    acc[i][j] += a[i] * b[j];
        }
    }

    // epilogue (N % 8 == 0 for all our shapes, so 8-wide groups are all-or-nothing)
    const int nb = n0 + tx * 8;
    if (nb < N) {
        float bb[8];
#pragma unroll
        for (int j = 0; j < 8; j++) bb[j] = bias[nb + j];
#pragma unroll
        for (int i = 0; i < 8; i++) {
            const int m = m0 + ty * 8 + i;
            float4 r0 = make_float4(acc[i][0] + bb[0], acc[i][1] + bb[1],
                                    acc[i][2] + bb[2], acc[i][3] + bb[3]);
            float4 r1 = make_float4(acc[i][4] + bb[4], acc[i][5] + bb[5],
                                    acc[i][6] + bb[6], acc[i][7] + bb[7]);
            *(float4*)(C + (size_t)m * N + nb) = r0;
            *(float4*)(C + (size_t)m * N + nb + 4) = r1;
        }
    }
}

// ============================================================================
// Flash attention (causal, GQA 8:1), fp32.
// Grid: (32 q-blocks, 64 heads). Block: 256 threads = 8 warps.
// Each warp owns 8 query rows; each lane owns key columns {lane, lane+32}
// for scores and output dims {2*lane, 2*lane+1}.
// smem: Qs 16KB + KPs 16KB (K tile, XOR-swizzled; reused as P tile) + Vs 16KB.
// ============================================================================
__global__ __launch_bounds__(256) void flash_attn(
    const float* __restrict__ Q, const float* __restrict__ K,
    const float* __restrict__ V, float* __restrict__ O)
{
    __shared__ float Qs[64][64];
    __shared__ float KPs[64][64];   // K (swizzled) then P (unswizzled)
    __shared__ float Vs[64][64];

    const int h   = blockIdx.y;
    const int qb  = blockIdx.x;
    const int kvh = h >> 3;
    const int tid  = threadIdx.x;
    const int w    = tid >> 5;
    const int lane = tid & 31;
    const int r0 = qb * 64;
    const int tA = lane;
    const int tB = lane + 32;

    // load Q tile [64 rows x 64 dims]
#pragma unroll
    for (int i = 0; i < 4; i++) {
        int idx = tid + i * 256;
        int r = idx >> 4;
        int c4 = idx & 15;
        float4 qv = *(const float4*)(Q + (size_t)(r0 + r) * QDIM + h * HDIM + c4 * 4);
        *(float4*)&Qs[r][c4 * 4] = qv;
    }

    float m_i[8], l_i[8], o0[8], o1[8];
#pragma unroll
    for (int r = 0; r < 8; r++) {
        m_i[r] = -1e30f; l_i[r] = 0.0f; o0[r] = 0.0f; o1[r] = 0.0f;
    }

    for (int j = 0; j <= qb; j++) {
        const int t0g = j * 64;

        __syncthreads();  // prior PV reads of Vs / KPs(P) finished
        // load K tile (swizzled: float4 col c4 stored at c4 ^ (t&7)) and V tile
#pragma unroll
        for (int i = 0; i < 4; i++) {
            int idx = tid + i * 256;
            int t = idx >> 4;
            int c4 = idx & 15;
            float4 kvv = *(const float4*)(K + (size_t)(t0g + t) * KVDIM + kvh * HDIM + c4 * 4);
            float4 vvv = *(const float4*)(V + (size_t)(t0g + t) * KVDIM + kvh * HDIM + c4 * 4);
            *(float4*)&KPs[t][(c4 ^ (t & 7)) * 4] = kvv;
            *(float4*)&Vs[t][c4 * 4] = vvv;
        }
        __syncthreads();

        // S = Q . K^T  for this warp's 8 rows, lane's 2 key columns
        float s0[8], s1[8];
#pragma unroll
        for (int r = 0; r < 8; r++) { s0[r] = 0.0f; s1[r] = 0.0f; }
#pragma unroll
        for (int c4 = 0; c4 < 16; c4++) {
            float4 ka = *(const float4*)&KPs[tA][(c4 ^ (tA & 7)) * 4];
            float4 kb = *(const float4*)&KPs[tB][(c4 ^ (tB & 7)) * 4];
#pragma unroll
            for (int r = 0; r < 8; r++) {
                float4 qv = *(const float4*)&Qs[w * 8 + r][c4 * 4];
                s0[r] += qv.x * ka.x; s0[r] += qv.y * ka.y;
                s0[r] += qv.z * ka.z; s0[r] += qv.w * ka.w;
                s1[r] += qv.x * kb.x; s1[r] += qv.y * kb.y;
                s1[r] += qv.z * kb.z; s1[r] += qv.w * kb.w;
            }
        }

        // online softmax update (registers only)
        const bool diag = (j == qb);
        float p0[8], p1[8];
#pragma unroll
        for (int r = 0; r < 8; r++) {
            float v0 = s0[r] * 0.125f;   // 1/sqrt(64)
            float v1 = s1[r] * 0.125f;
            const int rl = w * 8 + r;
            if (diag) {
                if (tA > rl) v0 = -1e30f;
                if (tB > rl) v1 = -1e30f;
            }
            float mx = fmaxf(v0, v1);
#pragma unroll
            for (int off = 16; off > 0; off >>= 1)
                mx = fmaxf(mx, __shfl_xor_sync(0xffffffffu, mx, off));
            const float mnew = fmaxf(m_i[r], mx);
            const float a = __expf(v0 - mnew);
            const float b = __expf(v1 - mnew);
            float ps = a + b;
#pragma unroll
            for (int off = 16; off > 0; off >>= 1)
                ps += __shfl_xor_sync(0xffffffffu, ps, off);
            const float corr = __expf(m_i[r] - mnew);
            l_i[r] = l_i[r] * corr + ps;
            m_i[r] = mnew;
            o0[r] *= corr; o1[r] *= corr;
            p0[r] = a; p1[r] = b;
        }

        __syncthreads();  // all warps done reading KPs(K) -> safe to write P
#pragma unroll
        for (int r = 0; r < 8; r++) {
            KPs[w * 8 + r][tA] = p0[r];
            KPs[w * 8 + r][tB] = p1[r];
        }
        __syncwarp();

        // O += P . V  (lane owns output dims 2*lane, 2*lane+1)
#pragma unroll
        for (int t4 = 0; t4 < 16; t4++) {
            float2 va = *(const float2*)&Vs[t4 * 4 + 0][lane * 2];
            float2 vb = *(const float2*)&Vs[t4 * 4 + 1][lane * 2];
            float2 vc = *(const float2*)&Vs[t4 * 4 + 2][lane * 2];
            float2 vd = *(const float2*)&Vs[t4 * 4 + 3][lane * 2];
#pragma unroll
            for (int r = 0; r < 8; r++) {
                float4 p = *(const float4*)&KPs[w * 8 + r][t4 * 4];
                o0[r] += p.x * va.x + p.y * vb.x + p.z * vc.x + p.w * vd.x;
                o1[r] += p.x * va.y + p.y * vb.y + p.z * vc.y + p.w * vd.y;
            }
        }
    }

    // write normalized output
#pragma unroll
    for (int r = 0; r < 8; r++) {
        const float inv = 1.0f / l_i[r];
        const int row = r0 + w * 8 + r;
        float2 res = make_float2(o0[r] * inv, o1[r] * inv);
        *(float2*)(O + (size_t)row * QDIM + h * HDIM + lane * 2) = res;
    }
}

// ============================================================================
// launch
// Inputs: 0 hidden_states [1,2048,2880], 1 attention_mask (unused),
//         2 Wq [4096,2880], 3 bq, 4 Wk [512,2880], 5 bk, 6 Wv [512,2880],
//         7 bv, 8 Wo [2880,4096], 9 bo
// Output: [1,2048,2880] fp32
// ============================================================================
extern "C" void kernel_launch(void* const* d_in, const int* in_sizes, int n_in,
                              void* d_out, int out_size)
{
    (void)in_sizes; (void)n_in; (void)out_size;
    const float* hs = (const float*)d_in[0];
    const float* Wq = (const float*)d_in[2];
    const float* bq = (const float*)d_in[3];
    const float* Wk = (const float*)d_in[4];
    const float* bk = (const float*)d_in[5];
    const float* Wv = (const float*)d_in[6];
    const float* bv = (const float*)d_in[7];
    const float* Wo = (const float*)d_in[8];
    const float* bo = (const float*)d_in[9];
    float* out = (float*)d_out;

    float *qp, *kp, *vp, *aop;
    cudaGetSymbolAddress((void**)&qp, g_q);
    cudaGetSymbolAddress((void**)&kp, g_k);
    cudaGetSymbolAddress((void**)&vp, g_v);
    cudaGetSymbolAddress((void**)&aop, g_ao);

    dim3 blk(256);
    // QKV projections
    sgemm_bias<<<dim3(QDIM / 128, SLEN / 128), blk>>>(hs, Wq, bq, qp, SLEN, QDIM, HIDDEN);
    sgemm_bias<<<dim3(KVDIM / 128, SLEN / 128), blk>>>(hs, Wk, bk, kp, SLEN, KVDIM, HIDDEN);
    sgemm_bias<<<dim3(KVDIM / 128, SLEN / 128), blk>>>(hs, Wv, bv, vp, SLEN, KVDIM, HIDDEN);
    // attention
    flash_attn<<<dim3(SLEN / 64, NHEADS), blk>>>(qp, kp, vp, aop);
    // output projection (N=2880 not a multiple of 128 -> guarded tiles)
    sgemm_bias<<<dim3((HIDDEN + 127) / 128, SLEN / 128), blk>>>(aop, Wo, bo, out, SLEN, HIDDEN, QDIM);
}

// round 2
// speedup vs baseline: 2.1888x; 2.1888x over previous
#include <cuda_runtime.h>
#include <math.h>

#define SLEN 2048
#define HIDDEN 2880
#define NHEADS 64
#define NKV 8
#define HDIM 64
#define QDIM (NHEADS * HDIM)   /* 4096 */
#define KVDIM (NKV * HDIM)     /* 512  */

// -------------------- scratch (static device globals; no allocation) ---------
__device__ float g_q[SLEN * QDIM];    // 32 MB
__device__ float g_k[SLEN * KVDIM];   //  4 MB
__device__ float g_v[SLEN * KVDIM];   //  4 MB
__device__ float g_ao[SLEN * QDIM];   // 32 MB

// ---------------------------------------------------------------------------
// helpers
// ---------------------------------------------------------------------------
__device__ __forceinline__ unsigned f2tf(float f) {
    unsigned u;
    asm("cvt.rna.tf32.f32 %0, %1;" : "=r"(u) : "f"(f));
    return u;
}

__device__ __forceinline__ void mma_tf32(float* c, const unsigned* a,
                                         unsigned b0, unsigned b1) {
    asm volatile(
        "mma.sync.aligned.m16n8k8.row.col.f32.tf32.tf32.f32 "
        "{%0,%1,%2,%3}, {%4,%5,%6,%7}, {%8,%9}, {%0,%1,%2,%3};"
        : "+f"(c[0]), "+f"(c[1]), "+f"(c[2]), "+f"(c[3])
        : "r"(a[0]), "r"(a[1]), "r"(a[2]), "r"(a[3]), "r"(b0), "r"(b1));
}

#define CP_ASYNC16(dst, src, ok)                                         \
    asm volatile("cp.async.cg.shared.global [%0], [%1], 16, %2;"         \
                 :: "r"(dst), "l"(src), "r"((ok) ? 16 : 0))
#define CP_COMMIT() asm volatile("cp.async.commit_group;")
#define CP_WAIT0()  asm volatile("cp.async.wait_group 0;")

// ============================================================================
// Tensor-core SGEMM (tf32): C[m][n] = sum_k A[m][k] * W[n][k] + bias[n]
// A: [M,K] row-major, W: [N,K] row-major. 128x128 tile, BK=32, 256 threads.
// 8 warps, each owns a 32x64 warp-tile = 2 (m16) x 8 (n8) mma fragments.
// smem: A/B tiles stored [row][36] (pad 36 -> conflict-free fragment LDS).
// Double-buffered via cp.async. M % 128 == 0, K % 32 == 0; N guarded.
// ============================================================================
#define BK 32
#define LDP 36                       /* padded row stride in floats */
#define TILE_F (128 * LDP)           /* floats per tile buffer */

__global__ __launch_bounds__(256) void sgemm_tc(
    const float* __restrict__ A, const float* __restrict__ W,
    const float* __restrict__ bias, float* __restrict__ C,
    int M, int N, int Kdim)
{
    extern __shared__ float sm[];
    // layout: [stage][A(128*36) | B(128*36)]
    const int tid  = threadIdx.x;
    const int lane = tid & 31;
    const int w    = tid >> 5;
    const int wm   = (w & 3) * 32;   // warp m offset in tile
    const int wn   = (w >> 2) * 64;  // warp n offset in tile
    const int m0   = blockIdx.y * 128;
    const int n0   = blockIdx.x * 128;

    const int g  = lane >> 2;        // 0..7
    const int tg = lane & 3;         // 0..3

    float acc[2][8][4];
#pragma unroll
    for (int i = 0; i < 2; i++)
#pragma unroll
        for (int j = 0; j < 8; j++)
#pragma unroll
            for (int q = 0; q < 4; q++) acc[i][j][q] = 0.0f;

    // loader indices: idx = it*256 + tid -> row = idx>>3 (0..127), kc = idx&7
    const int lrow = tid >> 3;       // base row for it=0 (rows advance by 32/it)
    const int lkc  = tid & 7;

    auto issue_tile = [&](int k0, int stage) {
        float* As = sm + stage * (2 * TILE_F);
        float* Bs = As + TILE_F;
#pragma unroll
        for (int it = 0; it < 4; it++) {
            const int row = lrow + it * 32;
            const unsigned da = (unsigned)__cvta_generic_to_shared(
                &As[row * LDP + lkc * 4]);
            const float* sa = A + (size_t)(m0 + row) * Kdim + k0 + lkc * 4;
            CP_ASYNC16(da, sa, 1);
            const unsigned db = (unsigned)__cvta_generic_to_shared(
                &Bs[row * LDP + lkc * 4]);
            const int nrow = n0 + row;
            const float* sb = W + (size_t)(nrow < N ? nrow : 0) * Kdim + k0 + lkc * 4;
            CP_ASYNC16(db, sb, nrow < N);
        }
        CP_COMMIT();
    };

    const int KT = Kdim / BK;
    int stage = 0;
    issue_tile(0, 0);

    for (int t = 0; t < KT; t++) {
        CP_WAIT0();
        __syncthreads();
        if (t + 1 < KT) issue_tile((t + 1) * BK, stage ^ 1);

        const float* As = sm + stage * (2 * TILE_F);
        const float* Bs = As + TILE_F;

#pragma unroll
        for (int kk = 0; kk < BK; kk += 8) {
            unsigned a[2][4];
#pragma unroll
            for (int mi = 0; mi < 2; mi++) {
                const int r = wm + mi * 16 + g;
                const int c = kk + tg;
                a[mi][0] = f2tf(As[r * LDP + c]);
                a[mi][1] = f2tf(As[(r + 8) * LDP + c]);
                a[mi][2] = f2tf(As[r * LDP + c + 4]);
                a[mi][3] = f2tf(As[(r + 8) * LDP + c + 4]);
            }
#pragma unroll
            for (int nj = 0; nj < 8; nj++) {
                const int n = wn + nj * 8 + g;
                const unsigned b0 = f2tf(Bs[n * LDP + kk + tg]);
                const unsigned b1 = f2tf(Bs[n * LDP + kk + tg + 4]);
                mma_tf32(acc[0][nj], a[0], b0, b1);
                mma_tf32(acc[1][nj], a[1], b0, b1);
            }
        }
        __syncthreads();
        stage ^= 1;
    }

    // epilogue: c0,c1 -> (row, 2*tg), c2,c3 -> (row+8, 2*tg)
#pragma unroll
    for (int mi = 0; mi < 2; mi++) {
#pragma unroll
        for (int nj = 0; nj < 8; nj++) {
            const int col = n0 + wn + nj * 8 + 2 * tg;
            if (col < N) {
                const float b0 = bias[col];
                const float b1 = bias[col + 1];
                const int row = m0 + wm + mi * 16 + g;
                float2 r0 = make_float2(acc[mi][nj][0] + b0, acc[mi][nj][1] + b1);
                float2 r1 = make_float2(acc[mi][nj][2] + b0, acc[mi][nj][3] + b1);
                *(float2*)(C + (size_t)row * N + col) = r0;
                *(float2*)(C + (size_t)(row + 8) * N + col) = r1;
            }
        }
    }
}

// ============================================================================
// Flash attention (causal, GQA 8:1), fp32 (unchanged from R1 baseline).
// ============================================================================
__global__ __launch_bounds__(256) void flash_attn(
    const float* __restrict__ Q, const float* __restrict__ K,
    const float* __restrict__ V, float* __restrict__ O)
{
    __shared__ float Qs[64][64];
    __shared__ float KPs[64][64];
    __shared__ float Vs[64][64];

    const int h   = blockIdx.y;
    const int qb  = blockIdx.x;
    const int kvh = h >> 3;
    const int tid  = threadIdx.x;
    const int w    = tid >> 5;
    const int lane = tid & 31;
    const int r0 = qb * 64;
    const int tA = lane;
    const int tB = lane + 32;

#pragma unroll
    for (int i = 0; i < 4; i++) {
        int idx = tid + i * 256;
        int r = idx >> 4;
        int c4 = idx & 15;
        float4 qv = *(const float4*)(Q + (size_t)(r0 + r) * QDIM + h * HDIM + c4 * 4);
        *(float4*)&Qs[r][c4 * 4] = qv;
    }

    float m_i[8], l_i[8], o0[8], o1[8];
#pragma unroll
    for (int r = 0; r < 8; r++) {
        m_i[r] = -1e30f; l_i[r] = 0.0f; o0[r] = 0.0f; o1[r] = 0.0f;
    }

    for (int j = 0; j <= qb; j++) {
        const int t0g = j * 64;

        __syncthreads();
#pragma unroll
        for (int i = 0; i < 4; i++) {
            int idx = tid + i * 256;
            int t = idx >> 4;
            int c4 = idx & 15;
            float4 kvv = *(const float4*)(K + (size_t)(t0g + t) * KVDIM + kvh * HDIM + c4 * 4);
            float4 vvv = *(const float4*)(V + (size_t)(t0g + t) * KVDIM + kvh * HDIM + c4 * 4);
            *(float4*)&KPs[t][(c4 ^ (t & 7)) * 4] = kvv;
            *(float4*)&Vs[t][c4 * 4] = vvv;
        }
        __syncthreads();

        float s0[8], s1[8];
#pragma unroll
        for (int r = 0; r < 8; r++) { s0[r] = 0.0f; s1[r] = 0.0f; }
#pragma unroll
        for (int c4 = 0; c4 < 16; c4++) {
            float4 ka = *(const float4*)&KPs[tA][(c4 ^ (tA & 7)) * 4];
            float4 kb = *(const float4*)&KPs[tB][(c4 ^ (tB & 7)) * 4];
#pragma unroll
            for (int r = 0; r < 8; r++) {
                float4 qv = *(const float4*)&Qs[w * 8 + r][c4 * 4];
                s0[r] += qv.x * ka.x; s0[r] += qv.y * ka.y;
                s0[r] += qv.z * ka.z; s0[r] += qv.w * ka.w;
                s1[r] += qv.x * kb.x; s1[r] += qv.y * kb.y;
                s1[r] += qv.z * kb.z; s1[r] += qv.w * kb.w;
            }
        }

        const bool diag = (j == qb);
        float p0[8], p1[8];
#pragma unroll
        for (int r = 0; r < 8; r++) {
            float v0 = s0[r] * 0.125f;
            float v1 = s1[r] * 0.125f;
            const int rl = w * 8 + r;
            if (diag) {
                if (tA > rl) v0 = -1e30f;
                if (tB > rl) v1 = -1e30f;
            }
            float mx = fmaxf(v0, v1);
#pragma unroll
            for (int off = 16; off > 0; off >>= 1)
                mx = fmaxf(mx, __shfl_xor_sync(0xffffffffu, mx, off));
            const float mnew = fmaxf(m_i[r], mx);
            const float a = __expf(v0 - mnew);
            const float b = __expf(v1 - mnew);
            float ps = a + b;
#pragma unroll
            for (int off = 16; off > 0; off >>= 1)
                ps += __shfl_xor_sync(0xffffffffu, ps, off);
            const float corr = __expf(m_i[r] - mnew);
            l_i[r] = l_i[r] * corr + ps;
            m_i[r] = mnew;
            o0[r] *= corr; o1[r] *= corr;
            p0[r] = a; p1[r] = b;
        }

        __syncthreads();
#pragma unroll
        for (int r = 0; r < 8; r++) {
            KPs[w * 8 + r][tA] = p0[r];
            KPs[w * 8 + r][tB] = p1[r];
        }
        __syncwarp();

#pragma unroll
        for (int t4 = 0; t4 < 16; t4++) {
            float2 va = *(const float2*)&Vs[t4 * 4 + 0][lane * 2];
            float2 vb = *(const float2*)&Vs[t4 * 4 + 1][lane * 2];
            float2 vc = *(const float2*)&Vs[t4 * 4 + 2][lane * 2];
            float2 vd = *(const float2*)&Vs[t4 * 4 + 3][lane * 2];
#pragma unroll
            for (int r = 0; r < 8; r++) {
                float4 p = *(const float4*)&KPs[w * 8 + r][t4 * 4];
                o0[r] += p.x * va.x + p.y * vb.x + p.z * vc.x + p.w * vd.x;
                o1[r] += p.x * va.y + p.y * vb.y + p.z * vc.y + p.w * vd.y;
            }
        }
    }

#pragma unroll
    for (int r = 0; r < 8; r++) {
        const float inv = 1.0f / l_i[r];
        const int row = r0 + w * 8 + r;
        float2 res = make_float2(o0[r] * inv, o1[r] * inv);
        *(float2*)(O + (size_t)row * QDIM + h * HDIM + lane * 2) = res;
    }
}

// ============================================================================
// launch
// ============================================================================
extern "C" void kernel_launch(void* const* d_in, const int* in_sizes, int n_in,
                              void* d_out, int out_size)
{
    (void)in_sizes; (void)n_in; (void)out_size;
    const float* hs = (const float*)d_in[0];
    const float* Wq = (const float*)d_in[2];
    const float* bq = (const float*)d_in[3];
    const float* Wk = (const float*)d_in[4];
    const float* bk = (const float*)d_in[5];
    const float* Wv = (const float*)d_in[6];
    const float* bv = (const float*)d_in[7];
    const float* Wo = (const float*)d_in[8];
    const float* bo = (const float*)d_in[9];
    float* out = (float*)d_out;

    float *qp, *kp, *vp, *aop;
    cudaGetSymbolAddress((void**)&qp, g_q);
    cudaGetSymbolAddress((void**)&kp, g_k);
    cudaGetSymbolAddress((void**)&vp, g_v);
    cudaGetSymbolAddress((void**)&aop, g_ao);

    const int smem_bytes = 2 * 2 * TILE_F * (int)sizeof(float);  // 73728
    static bool attr_set = false;
    if (!attr_set) {
        cudaFuncSetAttribute(sgemm_tc,
                             cudaFuncAttributeMaxDynamicSharedMemorySize,
                             smem_bytes);
        attr_set = true;
    }

    dim3 blk(256);
    sgemm_tc<<<dim3(QDIM / 128, SLEN / 128), blk, smem_bytes>>>(
        hs, Wq, bq, qp, SLEN, QDIM, HIDDEN);
    sgemm_tc<<<dim3(KVDIM / 128, SLEN / 128), blk, smem_bytes>>>(
        hs, Wk, bk, kp, SLEN, KVDIM, HIDDEN);
    sgemm_tc<<<dim3(KVDIM / 128, SLEN / 128), blk, smem_bytes>>>(
        hs, Wv, bv, vp, SLEN, KVDIM, HIDDEN);
    flash_attn<<<dim3(SLEN / 64, NHEADS), blk>>>(qp, kp, vp, aop);
    sgemm_tc<<<dim3((HIDDEN + 127) / 128, SLEN / 128), blk, smem_bytes>>>(
        aop, Wo, bo, out, SLEN, HIDDEN, QDIM);
}

// round 3
// speedup vs baseline: 3.3787x; 1.5436x over previous
#include <cuda_runtime.h>
#include <math.h>

#define SLEN 2048
#define HIDDEN 2880
#define NHEADS 64
#define NKV 8
#define HDIM 64
#define QDIM (NHEADS * HDIM)   /* 4096 */
#define KVDIM (NKV * HDIM)     /* 512  */

// -------------------- scratch (static device globals; no allocation) ---------
__device__ float g_q[SLEN * QDIM];    // 32 MB
__device__ float g_k[SLEN * KVDIM];   //  4 MB
__device__ float g_v[SLEN * KVDIM];   //  4 MB
__device__ float g_ao[SLEN * QDIM];   // 32 MB

// ---------------------------------------------------------------------------
// helpers
// ---------------------------------------------------------------------------
__device__ __forceinline__ unsigned f2tf(float f) {
    unsigned u;
    asm("cvt.rna.tf32.f32 %0, %1;" : "=r"(u) : "f"(f));
    return u;
}

__device__ __forceinline__ void mma_tf32(float* c, const unsigned* a,
                                         unsigned b0, unsigned b1) {
    asm volatile(
        "mma.sync.aligned.m16n8k8.row.col.f32.tf32.tf32.f32 "
        "{%0,%1,%2,%3}, {%4,%5,%6,%7}, {%8,%9}, {%0,%1,%2,%3};"
        : "+f"(c[0]), "+f"(c[1]), "+f"(c[2]), "+f"(c[3])
        : "r"(a[0]), "r"(a[1]), "r"(a[2]), "r"(a[3]), "r"(b0), "r"(b1));
}

#define CP_ASYNC16(dst, src, ok)                                         \
    asm volatile("cp.async.cg.shared.global [%0], [%1], 16, %2;"         \
                 :: "r"(dst), "l"(src), "r"((ok) ? 16 : 0))
#define CP_COMMIT() asm volatile("cp.async.commit_group;")

// ============================================================================
// Tensor-core SGEMM (tf32) — unchanged from R2 (passing, ~92 TF/s).
// ============================================================================
#define BK 32
#define LDP 36
#define TILE_F (128 * LDP)

__global__ __launch_bounds__(256) void sgemm_tc(
    const float* __restrict__ A, const float* __restrict__ W,
    const float* __restrict__ bias, float* __restrict__ C,
    int M, int N, int Kdim)
{
    extern __shared__ float sm[];
    const int tid  = threadIdx.x;
    const int lane = tid & 31;
    const int w    = tid >> 5;
    const int wm   = (w & 3) * 32;
    const int wn   = (w >> 2) * 64;
    const int m0   = blockIdx.y * 128;
    const int n0   = blockIdx.x * 128;

    const int g  = lane >> 2;
    const int tg = lane & 3;

    float acc[2][8][4];
#pragma unroll
    for (int i = 0; i < 2; i++)
#pragma unroll
        for (int j = 0; j < 8; j++)
#pragma unroll
            for (int q = 0; q < 4; q++) acc[i][j][q] = 0.0f;

    const int lrow = tid >> 3;
    const int lkc  = tid & 7;

    auto issue_tile = [&](int k0, int stage) {
        float* As = sm + stage * (2 * TILE_F);
        float* Bs = As + TILE_F;
#pragma unroll
        for (int it = 0; it < 4; it++) {
            const int row = lrow + it * 32;
            const unsigned da = (unsigned)__cvta_generic_to_shared(
                &As[row * LDP + lkc * 4]);
            const float* sa = A + (size_t)(m0 + row) * Kdim + k0 + lkc * 4;
            CP_ASYNC16(da, sa, 1);
            const unsigned db = (unsigned)__cvta_generic_to_shared(
                &Bs[row * LDP + lkc * 4]);
            const int nrow = n0 + row;
            const float* sb = W + (size_t)(nrow < N ? nrow : 0) * Kdim + k0 + lkc * 4;
            CP_ASYNC16(db, sb, nrow < N);
        }
        CP_COMMIT();
    };

    const int KT = Kdim / BK;
    int stage = 0;
    issue_tile(0, 0);

    for (int t = 0; t < KT; t++) {
        asm volatile("cp.async.wait_group 0;");
        __syncthreads();
        if (t + 1 < KT) issue_tile((t + 1) * BK, stage ^ 1);

        const float* As = sm + stage * (2 * TILE_F);
        const float* Bs = As + TILE_F;

#pragma unroll
        for (int kk = 0; kk < BK; kk += 8) {
            unsigned a[2][4];
#pragma unroll
            for (int mi = 0; mi < 2; mi++) {
                const int r = wm + mi * 16 + g;
                const int c = kk + tg;
                a[mi][0] = f2tf(As[r * LDP + c]);
                a[mi][1] = f2tf(As[(r + 8) * LDP + c]);
                a[mi][2] = f2tf(As[r * LDP + c + 4]);
                a[mi][3] = f2tf(As[(r + 8) * LDP + c + 4]);
            }
#pragma unroll
            for (int nj = 0; nj < 8; nj++) {
                const int n = wn + nj * 8 + g;
                const unsigned b0 = f2tf(Bs[n * LDP + kk + tg]);
                const unsigned b1 = f2tf(Bs[n * LDP + kk + tg + 4]);
                mma_tf32(acc[0][nj], a[0], b0, b1);
                mma_tf32(acc[1][nj], a[1], b0, b1);
            }
        }
        __syncthreads();
        stage ^= 1;
    }

#pragma unroll
    for (int mi = 0; mi < 2; mi++) {
#pragma unroll
        for (int nj = 0; nj < 8; nj++) {
            const int col = n0 + wn + nj * 8 + 2 * tg;
            if (col < N) {
                const float b0 = bias[col];
                const float b1 = bias[col + 1];
                const int row = m0 + wm + mi * 16 + g;
                float2 r0 = make_float2(acc[mi][nj][0] + b0, acc[mi][nj][1] + b1);
                float2 r1 = make_float2(acc[mi][nj][2] + b0, acc[mi][nj][3] + b1);
                *(float2*)(C + (size_t)row * N + col) = r0;
                *(float2*)(C + (size_t)(row + 8) * N + col) = r1;
            }
        }
    }
}

// ============================================================================
// Flash attention on tensor cores (tf32 mma), causal, GQA 8:1.
// Grid: (32 q-blocks, 64 heads). Block: 128 threads = 4 warps.
// Warp w owns q-rows [w*16, w*16+16). Q held in registers as A-fragments.
// K/V double-buffered via cp.async. P routed through per-warp-private smem.
// Pads: K/P stride 68 (frag LDS banks = g*4+tg: conflict-free),
//       V stride 72 (banks = tg*8+g: conflict-free).
// ============================================================================
#define FKP 68
#define FVP 72
#define KS_F (64 * FKP)   /* 4352 floats */
#define VS_F (64 * FVP)   /* 4608 floats */
#define FLASH_SMEM ((2 * KS_F + 2 * VS_F + KS_F) * 4)  /* 89088 bytes */

__global__ __launch_bounds__(128) void flash_attn_tc(
    const float* __restrict__ Q, const float* __restrict__ K,
    const float* __restrict__ V, float* __restrict__ O)
{
    extern __shared__ float fsm[];
    float* Ks = fsm;                       // 2 x [64][68]
    float* Vs = fsm + 2 * KS_F;            // 2 x [64][72]
    float* Ps = fsm + 2 * KS_F + 2 * VS_F; // [64][68] (Q stage, then P)

    const int h    = blockIdx.y;
    const int qb   = blockIdx.x;
    const int kvh  = h >> 3;
    const int tid  = threadIdx.x;
    const int w    = tid >> 5;
    const int lane = tid & 31;
    const int g    = lane >> 2;
    const int tg   = lane & 3;
    const int r0   = qb * 64;
    const int wr   = w * 16;

    // ---- stage Q tile through Ps (coalesced), then lift to A-fragments ----
#pragma unroll
    for (int i = 0; i < 8; i++) {
        int idx = tid + i * 128;
        int r = idx >> 4, c4 = idx & 15;
        *(float4*)&Ps[r * FKP + c4 * 4] =
            *(const float4*)(Q + (size_t)(r0 + r) * QDIM + h * HDIM + c4 * 4);
    }
    __syncthreads();

    unsigned qf[8][4];
#pragma unroll
    for (int kk = 0; kk < 8; kk++) {
        qf[kk][0] = f2tf(Ps[(wr + g) * FKP + kk * 8 + tg]);
        qf[kk][1] = f2tf(Ps[(wr + g + 8) * FKP + kk * 8 + tg]);
        qf[kk][2] = f2tf(Ps[(wr + g) * FKP + kk * 8 + tg + 4]);
        qf[kk][3] = f2tf(Ps[(wr + g + 8) * FKP + kk * 8 + tg + 4]);
    }

    float o[8][4];
#pragma unroll
    for (int nj = 0; nj < 8; nj++)
#pragma unroll
        for (int c = 0; c < 4; c++) o[nj][c] = 0.0f;
    float m_lo = -1e30f, m_hi = -1e30f, l_lo = 0.0f, l_hi = 0.0f;

    auto issue_kv = [&](int j, int buf) {
        const int t0 = j * 64;
        float* Kb = Ks + buf * KS_F;
        float* Vb = Vs + buf * VS_F;
#pragma unroll
        for (int i = 0; i < 8; i++) {
            int idx = tid + i * 128;
            int r = idx >> 4, c4 = idx & 15;
            const unsigned dk = (unsigned)__cvta_generic_to_shared(
                &Kb[r * FKP + c4 * 4]);
            CP_ASYNC16(dk, K + (size_t)(t0 + r) * KVDIM + kvh * HDIM + c4 * 4, 1);
            const unsigned dv = (unsigned)__cvta_generic_to_shared(
                &Vb[r * FVP + c4 * 4]);
            CP_ASYNC16(dv, V + (size_t)(t0 + r) * KVDIM + kvh * HDIM + c4 * 4, 1);
        }
        CP_COMMIT();
    };

    issue_kv(0, 0);
    int buf = 0;

    for (int j = 0; j <= qb; j++) {
        const bool more = (j < qb);
        if (more) {
            issue_kv(j + 1, buf ^ 1);
            asm volatile("cp.async.wait_group 1;");
        } else {
            asm volatile("cp.async.wait_group 0;");
        }
        __syncthreads();

        const float* Kb = Ks + buf * KS_F;
        const float* Vb = Vs + buf * VS_F;

        // ---- S = Q . K^T ----
        float s[8][4];
#pragma unroll
        for (int nj = 0; nj < 8; nj++)
#pragma unroll
            for (int c = 0; c < 4; c++) s[nj][c] = 0.0f;

#pragma unroll
        for (int kk = 0; kk < 8; kk++) {
#pragma unroll
            for (int nj = 0; nj < 8; nj++) {
                const unsigned b0 = f2tf(Kb[(nj * 8 + g) * FKP + kk * 8 + tg]);
                const unsigned b1 = f2tf(Kb[(nj * 8 + g) * FKP + kk * 8 + tg + 4]);
                mma_tf32(s[nj], qf[kk], b0, b1);
            }
        }

        // ---- scale + causal mask ----
        const int t0 = j * 64;
        const bool diag = (j == qb);
        const int row_lo = r0 + wr + g;
        const int row_hi = row_lo + 8;
#pragma unroll
        for (int nj = 0; nj < 8; nj++) {
            const int cb = t0 + nj * 8 + 2 * tg;
            float v0 = s[nj][0] * 0.125f;
            float v1 = s[nj][1] * 0.125f;
            float v2 = s[nj][2] * 0.125f;
            float v3 = s[nj][3] * 0.125f;
            if (diag) {
                if (cb     > row_lo) v0 = -1e30f;
                if (cb + 1 > row_lo) v1 = -1e30f;
                if (cb     > row_hi) v2 = -1e30f;
                if (cb + 1 > row_hi) v3 = -1e30f;
            }
            s[nj][0] = v0; s[nj][1] = v1; s[nj][2] = v2; s[nj][3] = v3;
        }

        // ---- online softmax (row stats across the quad) ----
        float mx_lo = -1e30f, mx_hi = -1e30f;
#pragma unroll
        for (int nj = 0; nj < 8; nj++) {
            mx_lo = fmaxf(mx_lo, fmaxf(s[nj][0], s[nj][1]));
            mx_hi = fmaxf(mx_hi, fmaxf(s[nj][2], s[nj][3]));
        }
        mx_lo = fmaxf(mx_lo, __shfl_xor_sync(0xffffffffu, mx_lo, 1));
        mx_lo = fmaxf(mx_lo, __shfl_xor_sync(0xffffffffu, mx_lo, 2));
        mx_hi = fmaxf(mx_hi, __shfl_xor_sync(0xffffffffu, mx_hi, 1));
        mx_hi = fmaxf(mx_hi, __shfl_xor_sync(0xffffffffu, mx_hi, 2));

        const float mn_lo = fmaxf(m_lo, mx_lo);
        const float mn_hi = fmaxf(m_hi, mx_hi);
        const float corr_lo = __expf(m_lo - mn_lo);
        const float corr_hi = __expf(m_hi - mn_hi);

        float sum_lo = 0.0f, sum_hi = 0.0f;
#pragma unroll
        for (int nj = 0; nj < 8; nj++) {
            s[nj][0] = __expf(s[nj][0] - mn_lo);
            s[nj][1] = __expf(s[nj][1] - mn_lo);
            s[nj][2] = __expf(s[nj][2] - mn_hi);
            s[nj][3] = __expf(s[nj][3] - mn_hi);
            sum_lo += s[nj][0] + s[nj][1];
            sum_hi += s[nj][2] + s[nj][3];
        }
        sum_lo += __shfl_xor_sync(0xffffffffu, sum_lo, 1);
        sum_lo += __shfl_xor_sync(0xffffffffu, sum_lo, 2);
        sum_hi += __shfl_xor_sync(0xffffffffu, sum_hi, 1);
        sum_hi += __shfl_xor_sync(0xffffffffu, sum_hi, 2);

        l_lo = l_lo * corr_lo + sum_lo;
        l_hi = l_hi * corr_hi + sum_hi;
        m_lo = mn_lo;
        m_hi = mn_hi;

#pragma unroll
        for (int nj = 0; nj < 8; nj++) {
            o[nj][0] *= corr_lo; o[nj][1] *= corr_lo;
            o[nj][2] *= corr_hi; o[nj][3] *= corr_hi;
        }

        // ---- P -> smem (per-warp-private rows; no cross-warp hazard) ----
#pragma unroll
        for (int nj = 0; nj < 8; nj++) {
            *(float2*)&Ps[(wr + g) * FKP + nj * 8 + 2 * tg] =
                make_float2(s[nj][0], s[nj][1]);
            *(float2*)&Ps[(wr + g + 8) * FKP + nj * 8 + 2 * tg] =
                make_float2(s[nj][2], s[nj][3]);
        }
        __syncwarp();

        // ---- O += P . V ----
#pragma unroll
        for (int kk = 0; kk < 8; kk++) {
            unsigned a[4];
            a[0] = f2tf(Ps[(wr + g) * FKP + kk * 8 + tg]);
            a[1] = f2tf(Ps[(wr + g + 8) * FKP + kk * 8 + tg]);
            a[2] = f2tf(Ps[(wr + g) * FKP + kk * 8 + tg + 4]);
            a[3] = f2tf(Ps[(wr + g + 8) * FKP + kk * 8 + tg + 4]);
#pragma unroll
            for (int nj = 0; nj < 8; nj++) {
                const unsigned b0 = f2tf(Vb[(kk * 8 + tg) * FVP + nj * 8 + g]);
                const unsigned b1 = f2tf(Vb[(kk * 8 + tg + 4) * FVP + nj * 8 + g]);
                mma_tf32(o[nj], a, b0, b1);
            }
        }
        __syncthreads();   // all warps done with K/V buf before it is refilled
        buf ^= 1;
    }

    // ---- write normalized output ----
    const float inv_lo = 1.0f / l_lo;
    const float inv_hi = 1.0f / l_hi;
#pragma unroll
    for (int nj = 0; nj < 8; nj++) {
        const int col = h * HDIM + nj * 8 + 2 * tg;
        *(float2*)(O + (size_t)(r0 + wr + g) * QDIM + col) =
            make_float2(o[nj][0] * inv_lo, o[nj][1] * inv_lo);
        *(float2*)(O + (size_t)(r0 + wr + g + 8) * QDIM + col) =
            make_float2(o[nj][2] * inv_hi, o[nj][3] * inv_hi);
    }
}

// ============================================================================
// launch
// ============================================================================
extern "C" void kernel_launch(void* const* d_in, const int* in_sizes, int n_in,
                              void* d_out, int out_size)
{
    (void)in_sizes; (void)n_in; (void)out_size;
    const float* hs = (const float*)d_in[0];
    const float* Wq = (const float*)d_in[2];
    const float* bq = (const float*)d_in[3];
    const float* Wk = (const float*)d_in[4];
    const float* bk = (const float*)d_in[5];
    const float* Wv = (const float*)d_in[6];
    const float* bv = (const float*)d_in[7];
    const float* Wo = (const float*)d_in[8];
    const float* bo = (const float*)d_in[9];
    float* out = (float*)d_out;

    float *qp, *kp, *vp, *aop;
    cudaGetSymbolAddress((void**)&qp, g_q);
    cudaGetSymbolAddress((void**)&kp, g_k);
    cudaGetSymbolAddress((void**)&vp, g_v);
    cudaGetSymbolAddress((void**)&aop, g_ao);

    const int gemm_smem = 2 * 2 * TILE_F * (int)sizeof(float);  // 73728
    static bool attr_set = false;
    if (!attr_set) {
        cudaFuncSetAttribute(sgemm_tc,
                             cudaFuncAttributeMaxDynamicSharedMemorySize,
                             gemm_smem);
        cudaFuncSetAttribute(flash_attn_tc,
                             cudaFuncAttributeMaxDynamicSharedMemorySize,
                             FLASH_SMEM);
        attr_set = true;
    }

    sgemm_tc<<<dim3(QDIM / 128, SLEN / 128), 256, gemm_smem>>>(
        hs, Wq, bq, qp, SLEN, QDIM, HIDDEN);
    sgemm_tc<<<dim3(KVDIM / 128, SLEN / 128), 256, gemm_smem>>>(
        hs, Wk, bk, kp, SLEN, KVDIM, HIDDEN);
    sgemm_tc<<<dim3(KVDIM / 128, SLEN / 128), 256, gemm_smem>>>(
        hs, Wv, bv, vp, SLEN, KVDIM, HIDDEN);
    flash_attn_tc<<<dim3(SLEN / 64, NHEADS), 128, FLASH_SMEM>>>(qp, kp, vp, aop);
    sgemm_tc<<<dim3((HIDDEN + 127) / 128, SLEN / 128), 256, gemm_smem>>>(
        aop, Wo, bo, out, SLEN, HIDDEN, QDIM);
}

// round 5
// speedup vs baseline: 3.9058x; 1.1560x over previous
#include <cuda_runtime.h>
#include <cuda_fp16.h>
#include <math.h>
#include <stdint.h>

#define SLEN 2048
#define HIDDEN 2880
#define NHEADS 64
#define NKV 8
#define HDIM 64
#define QDIM (NHEADS * HDIM)   /* 4096 */
#define KVDIM (NKV * HDIM)     /* 512  */

// -------------------- scratch (static device globals; no allocation) ---------
__device__ float g_q[SLEN * QDIM];    // 32 MB
__device__ float g_k[SLEN * KVDIM];   //  4 MB
__device__ float g_v[SLEN * KVDIM];   //  4 MB
__device__ float g_ao[SLEN * QDIM];   // 32 MB

// ---------------------------------------------------------------------------
// helpers
// ---------------------------------------------------------------------------
__device__ __forceinline__ uint32_t h2pack(float x, float y) {
    __half2 h = __floats2half2_rn(x, y);
    return *(uint32_t*)&h;
}

// mma m16n8k16 f16 inputs, f32 accumulate
__device__ __forceinline__ void mma_f16(float* c, const uint32_t* a,
                                        uint32_t b0, uint32_t b1) {
    asm volatile(
        "mma.sync.aligned.m16n8k16.row.col.f32.f16.f16.f32 "
        "{%0,%1,%2,%3}, {%4,%5,%6,%7}, {%8,%9}, {%0,%1,%2,%3};"
        : "+f"(c[0]), "+f"(c[1]), "+f"(c[2]), "+f"(c[3])
        : "r"(a[0]), "r"(a[1]), "r"(a[2]), "r"(a[3]), "r"(b0), "r"(b1));
}

// ============================================================================
// FP16 tensor-core GEMM: C[m][n] = sum_k A[m][k]*W[n][k] + bias[n]
// A:[M,K], W:[N,K] row-major fp32. Tile 128x128, BK=32, 256 threads.
// Loader converts fp32 -> fp16 at STS; inner loop is pure LDS.32 + HMMA.
// smem rows padded to 40 halves: fragment LDS bank = 4g+tg (conflict-free).
// 8 warps, each a 32x64 warp tile = 2(m16) x 8(n8), kk=2 k16-steps per BK.
// ============================================================================
#define GLD 40   /* half stride per row */

__global__ __launch_bounds__(256) void hgemm(
    const float* __restrict__ A, const float* __restrict__ W,
    const float* __restrict__ bias, float* __restrict__ C,
    int M, int N, int Kdim)
{
    __shared__ __half Ah[2][128 * GLD];
    __shared__ __half Bh[2][128 * GLD];

    const int tid  = threadIdx.x;
    const int lane = tid & 31;
    const int w    = tid >> 5;
    const int wm   = (w & 3) * 32;
    const int wn   = (w >> 2) * 64;
    const int m0   = blockIdx.y * 128;
    const int n0   = blockIdx.x * 128;
    const int g    = lane >> 2;
    const int tg   = lane & 3;

    float acc[2][8][4];
#pragma unroll
    for (int i = 0; i < 2; i++)
#pragma unroll
        for (int j = 0; j < 8; j++)
#pragma unroll
            for (int q = 0; q < 4; q++) acc[i][j][q] = 0.0f;

    // loader: idx = tid + i*256 -> row = idx>>3 (0..127), c4 = idx&7
    const int lrow = tid >> 3;
    const int lc4  = tid & 7;

    float4 ra[4], rb[4];
    auto ldg_tile = [&](int k0) {
#pragma unroll
        for (int i = 0; i < 4; i++) {
            const int row = lrow + i * 32;
            ra[i] = *(const float4*)(A + (size_t)(m0 + row) * Kdim + k0 + lc4 * 4);
            const int nrow = n0 + row;
            rb[i] = *(const float4*)(W + (size_t)(nrow < N ? nrow : 0) * Kdim + k0 + lc4 * 4);
        }
    };
    auto sts_tile = [&](int buf) {
#pragma unroll
        for (int i = 0; i < 4; i++) {
            const int row = lrow + i * 32;
            uint2 va, vb;
            va.x = h2pack(ra[i].x, ra[i].y);
            va.y = h2pack(ra[i].z, ra[i].w);
            vb.x = h2pack(rb[i].x, rb[i].y);
            vb.y = h2pack(rb[i].z, rb[i].w);
            *(uint2*)&Ah[buf][row * GLD + lc4 * 4] = va;
            *(uint2*)&Bh[buf][row * GLD + lc4 * 4] = vb;
        }
    };

    const int KT = Kdim / 32;
    ldg_tile(0);
    sts_tile(0);
    __syncthreads();

    int buf = 0;
    for (int t = 0; t < KT; t++) {
        if (t + 1 < KT) ldg_tile((t + 1) * 32);

        const __half* Ab = Ah[buf];
        const __half* Bb = Bh[buf];
#pragma unroll
        for (int kk = 0; kk < 2; kk++) {
            uint32_t a[2][4];
#pragma unroll
            for (int mi = 0; mi < 2; mi++) {
                const int r = wm + mi * 16 + g;
                const int c = kk * 16 + 2 * tg;
                a[mi][0] = *(const uint32_t*)&Ab[r * GLD + c];
                a[mi][1] = *(const uint32_t*)&Ab[(r + 8) * GLD + c];
                a[mi][2] = *(const uint32_t*)&Ab[r * GLD + c + 8];
                a[mi][3] = *(const uint32_t*)&Ab[(r + 8) * GLD + c + 8];
            }
#pragma unroll
            for (int nj = 0; nj < 8; nj++) {
                const int nr = wn + nj * 8 + g;
                const int c = kk * 16 + 2 * tg;
                const uint32_t b0 = *(const uint32_t*)&Bb[nr * GLD + c];
                const uint32_t b1 = *(const uint32_t*)&Bb[nr * GLD + c + 8];
                mma_f16(acc[0][nj], a[0], b0, b1);
                mma_f16(acc[1][nj], a[1], b0, b1);
            }
        }
        __syncthreads();
        if (t + 1 < KT) {
            sts_tile(buf ^ 1);
            __syncthreads();
        }
        buf ^= 1;
    }

    // epilogue
#pragma unroll
    for (int mi = 0; mi < 2; mi++) {
#pragma unroll
        for (int nj = 0; nj < 8; nj++) {
            const int col = n0 + wn + nj * 8 + 2 * tg;
            if (col < N) {
                const float b0 = bias[col];
                const float b1 = bias[col + 1];
                const int row = m0 + wm + mi * 16 + g;
                *(float2*)(C + (size_t)row * N + col) =
                    make_float2(acc[mi][nj][0] + b0, acc[mi][nj][1] + b1);
                *(float2*)(C + (size_t)(row + 8) * N + col) =
                    make_float2(acc[mi][nj][2] + b0, acc[mi][nj][3] + b1);
            }
        }
    }
}

// ============================================================================
// FP16 flash attention (causal, GQA 8:1), warp-specialized.
// 256 threads: warps 0-3 consumers (16 q-rows each), warps 4-7 producers.
// Producers: LDG fp32 -> CVT fp16 -> STS, one KV tile ahead (double buffer).
// K stored [t][d] (72h pad); V stored transposed [d][t] (72h pad) so PV
// B-fragments are contiguous half2. P never touches smem (C-frag == A-frag).
// One __syncthreads per KV tile.
// ============================================================================
#define FLD 72   /* half stride */

__global__ __launch_bounds__(256) void flash_f16(
    const float* __restrict__ Q, const float* __restrict__ K,
    const float* __restrict__ V, float* __restrict__ O)
{
    __shared__ __half Qh[64 * FLD];
    __shared__ __half Kh[2][64 * FLD];
    __shared__ __half Vt[2][64 * FLD];

    const int h    = blockIdx.y;
    const int qb   = blockIdx.x;
    const int kvh  = h >> 3;
    const int tid  = threadIdx.x;
    const int wid  = tid >> 5;
    const int lane = tid & 31;
    const int g    = lane >> 2;
    const int tg   = lane & 3;
    const int r0   = qb * 64;
    const bool producer = (wid >= 4);
    const int ptid = tid - 128;          // producer thread id 0..127
    const int wr   = wid * 16;           // consumer q-row base (wid 0..3)

    auto load_kv = [&](int j, int buf) {
        const int t0 = j * 64;
        // K tile: coalesced float4 along d, store [t][d]
#pragma unroll
        for (int i = 0; i < 8; i++) {
            const int idx = ptid + i * 128;
            const int r = idx >> 4, c4 = idx & 15;
            float4 kv = *(const float4*)(K + (size_t)(t0 + r) * KVDIM + kvh * HDIM + c4 * 4);
            uint2 pk;
            pk.x = h2pack(kv.x, kv.y);
            pk.y = h2pack(kv.z, kv.w);
            *(uint2*)&Kh[buf][r * FLD + c4 * 4] = pk;
        }
        // V tile transposed: thread reads 4 t-consecutive scalars at fixed d,
        // stores one STS.64 row-chunk of Vt[d][t].
#pragma unroll
        for (int i = 0; i < 8; i++) {
            const int idx = ptid + i * 128;
            const int d = idx >> 4, tq = idx & 15;
            const float* vp = V + (size_t)(t0 + tq * 4) * KVDIM + kvh * HDIM + d;
            float v0 = vp[0];
            float v1 = vp[KVDIM];
            float v2 = vp[2 * KVDIM];
            float v3 = vp[3 * KVDIM];
            uint2 pv;
            pv.x = h2pack(v0, v1);
            pv.y = h2pack(v2, v3);
            *(uint2*)&Vt[buf][d * FLD + tq * 4] = pv;
        }
    };

    // ---- prologue: producers stage Q and KV tile 0 ----
    if (producer) {
#pragma unroll
        for (int i = 0; i < 8; i++) {
            const int idx = ptid + i * 128;
            const int r = idx >> 4, c4 = idx & 15;
            float4 qv = *(const float4*)(Q + (size_t)(r0 + r) * QDIM + h * HDIM + c4 * 4);
            uint2 pq;
            pq.x = h2pack(qv.x, qv.y);
            pq.y = h2pack(qv.z, qv.w);
            *(uint2*)&Qh[r * FLD + c4 * 4] = pq;
        }
        load_kv(0, 0);
    }
    __syncthreads();

    // consumers: lift Q to A-fragments (4 k16 chunks)
    uint32_t qf[4][4];
    float o[8][4];
    float m_lo = -1e30f, m_hi = -1e30f, l_lo = 0.0f, l_hi = 0.0f;
    if (!producer) {
#pragma unroll
        for (int kk = 0; kk < 4; kk++) {
            const int c = kk * 16 + 2 * tg;
            qf[kk][0] = *(const uint32_t*)&Qh[(wr + g) * FLD + c];
            qf[kk][1] = *(const uint32_t*)&Qh[(wr + g + 8) * FLD + c];
            qf[kk][2] = *(const uint32_t*)&Qh[(wr + g) * FLD + c + 8];
            qf[kk][3] = *(const uint32_t*)&Qh[(wr + g + 8) * FLD + c + 8];
        }
#pragma unroll
        for (int nj = 0; nj < 8; nj++)
#pragma unroll
            for (int c = 0; c < 4; c++) o[nj][c] = 0.0f;
    }

    for (int j = 0; j <= qb; j++) {
        const int buf = j & 1;
        if (producer) {
            if (j + 1 <= qb) load_kv(j + 1, buf ^ 1);
        } else {
            const __half* Kb = Kh[buf];
            const __half* Vb = Vt[buf];

            // ---- S = Q . K^T ----
            float s[8][4];
#pragma unroll
            for (int nj = 0; nj < 8; nj++)
#pragma unroll
                for (int c = 0; c < 4; c++) s[nj][c] = 0.0f;
#pragma unroll
            for (int kk = 0; kk < 4; kk++) {
                const int c = kk * 16 + 2 * tg;
#pragma unroll
                for (int nj = 0; nj < 8; nj++) {
                    const uint32_t b0 = *(const uint32_t*)&Kb[(nj * 8 + g) * FLD + c];
                    const uint32_t b1 = *(const uint32_t*)&Kb[(nj * 8 + g) * FLD + c + 8];
                    mma_f16(s[nj], qf[kk], b0, b1);
                }
            }

            // ---- scale + causal mask ----
            const int t0 = j * 64;
            const bool diag = (j == qb);
            const int row_lo = r0 + wr + g;
            const int row_hi = row_lo + 8;
#pragma unroll
            for (int nj = 0; nj < 8; nj++) {
                const int cb = t0 + nj * 8 + 2 * tg;
                float v0 = s[nj][0] * 0.125f;
                float v1 = s[nj][1] * 0.125f;
                float v2 = s[nj][2] * 0.125f;
                float v3 = s[nj][3] * 0.125f;
                if (diag) {
                    if (cb     > row_lo) v0 = -1e30f;
                    if (cb + 1 > row_lo) v1 = -1e30f;
                    if (cb     > row_hi) v2 = -1e30f;
                    if (cb + 1 > row_hi) v3 = -1e30f;
                }
                s[nj][0] = v0; s[nj][1] = v1; s[nj][2] = v2; s[nj][3] = v3;
            }

            // ---- online softmax ----
            float mx_lo = -1e30f, mx_hi = -1e30f;
#pragma unroll
            for (int nj = 0; nj < 8; nj++) {
                mx_lo = fmaxf(mx_lo, fmaxf(s[nj][0], s[nj][1]));
                mx_hi = fmaxf(mx_hi, fmaxf(s[nj][2], s[nj][3]));
            }
            mx_lo = fmaxf(mx_lo, __shfl_xor_sync(0xffffffffu, mx_lo, 1));
            mx_lo = fmaxf(mx_lo, __shfl_xor_sync(0xffffffffu, mx_lo, 2));
            mx_hi = fmaxf(mx_hi, __shfl_xor_sync(0xffffffffu, mx_hi, 1));
            mx_hi = fmaxf(mx_hi, __shfl_xor_sync(0xffffffffu, mx_hi, 2));

            const float mn_lo = fmaxf(m_lo, mx_lo);
            const float mn_hi = fmaxf(m_hi, mx_hi);
            const float corr_lo = __expf(m_lo - mn_lo);
            const float corr_hi = __expf(m_hi - mn_hi);

            float sum_lo = 0.0f, sum_hi = 0.0f;
#pragma unroll
            for (int nj = 0; nj < 8; nj++) {
                s[nj][0] = __expf(s[nj][0] - mn_lo);
                s[nj][1] = __expf(s[nj][1] - mn_lo);
                s[nj][2] = __expf(s[nj][2] - mn_hi);
                s[nj][3] = __expf(s[nj][3] - mn_hi);
                sum_lo += s[nj][0] + s[nj][1];
                sum_hi += s[nj][2] + s[nj][3];
            }
            sum_lo += __shfl_xor_sync(0xffffffffu, sum_lo, 1);
            sum_lo += __shfl_xor_sync(0xffffffffu, sum_lo, 2);
            sum_hi += __shfl_xor_sync(0xffffffffu, sum_hi, 1);
            sum_hi += __shfl_xor_sync(0xffffffffu, sum_hi, 2);

            l_lo = l_lo * corr_lo + sum_lo;
            l_hi = l_hi * corr_hi + sum_hi;
            m_lo = mn_lo;
            m_hi = mn_hi;
#pragma unroll
            for (int nj = 0; nj < 8; nj++) {
                o[nj][0] *= corr_lo; o[nj][1] *= corr_lo;
                o[nj][2] *= corr_hi; o[nj][3] *= corr_hi;
            }

            // ---- O += P . V  (P converted to A-fragments in registers) ----
#pragma unroll
            for (int kk = 0; kk < 4; kk++) {
                uint32_t pa[4];
                pa[0] = h2pack(s[2 * kk][0],     s[2 * kk][1]);
                pa[1] = h2pack(s[2 * kk][2],     s[2 * kk][3]);
                pa[2] = h2pack(s[2 * kk + 1][0], s[2 * kk + 1][1]);
                pa[3] = h2pack(s[2 * kk + 1][2], s[2 * kk + 1][3]);
                const int c = kk * 16 + 2 * tg;
#pragma unroll
                for (int nj = 0; nj < 8; nj++) {
                    const uint32_t b0 = *(const uint32_t*)&Vb[(nj * 8 + g) * FLD + c];
                    const uint32_t b1 = *(const uint32_t*)&Vb[(nj * 8 + g) * FLD + c + 8];
                    mma_f16(o[nj], pa, b0, b1);
                }
            }
        }
        __syncthreads();
    }

    // ---- write normalized output (consumers) ----
    if (!producer) {
        const float inv_lo = 1.0f / l_lo;
        const float inv_hi = 1.0f / l_hi;
#pragma unroll
        for (int nj = 0; nj < 8; nj++) {
            const int col = h * HDIM + nj * 8 + 2 * tg;
            *(float2*)(O + (size_t)(r0 + wr + g) * QDIM + col) =
                make_float2(o[nj][0] * inv_lo, o[nj][1] * inv_lo);
            *(float2*)(O + (size_t)(r0 + wr + g + 8) * QDIM + col) =
                make_float2(o[nj][2] * inv_hi, o[nj][3] * inv_hi);
        }
    }
}

// ============================================================================
// launch
// ============================================================================
extern "C" void kernel_launch(void* const* d_in, const int* in_sizes, int n_in,
                              void* d_out, int out_size)
{
    (void)in_sizes; (void)n_in; (void)out_size;
    const float* hs = (const float*)d_in[0];
    const float* Wq = (const float*)d_in[2];
    const float* bq = (const float*)d_in[3];
    const float* Wk = (const float*)d_in[4];
    const float* bk = (const float*)d_in[5];
    const float* Wv = (const float*)d_in[6];
    const float* bv = (const float*)d_in[7];
    const float* Wo = (const float*)d_in[8];
    const float* bo = (const float*)d_in[9];
    float* out = (float*)d_out;

    float *qp, *kp, *vp, *aop;
    cudaGetSymbolAddress((void**)&qp, g_q);
    cudaGetSymbolAddress((void**)&kp, g_k);
    cudaGetSymbolAddress((void**)&vp, g_v);
    cudaGetSymbolAddress((void**)&aop, g_ao);

    hgemm<<<dim3(QDIM / 128, SLEN / 128), 256>>>(hs, Wq, bq, qp, SLEN, QDIM, HIDDEN);
    hgemm<<<dim3(KVDIM / 128, SLEN / 128), 256>>>(hs, Wk, bk, kp, SLEN, KVDIM, HIDDEN);
    hgemm<<<dim3(KVDIM / 128, SLEN / 128), 256>>>(hs, Wv, bv, vp, SLEN, KVDIM, HIDDEN);
    flash_f16<<<dim3(SLEN / 64, NHEADS), 256>>>(qp, kp, vp, aop);
    hgemm<<<dim3((HIDDEN + 127) / 128, SLEN / 128), 256>>>(aop, Wo, bo, out, SLEN, HIDDEN, QDIM);
}

// round 6
// speedup vs baseline: 5.3686x; 1.3745x over previous
#include <cuda_runtime.h>
#include <cuda_fp16.h>
#include <math.h>
#include <stdint.h>

#define SLEN 2048
#define HIDDEN 2880
#define NHEADS 64
#define NKV 8
#define HDIM 64
#define QDIM (NHEADS * HDIM)   /* 4096 */
#define KVDIM (NKV * HDIM)     /* 512  */

// -------------------- scratch (static device globals; no allocation) ---------
__device__ __half g_qh[SLEN * QDIM];    // 16 MB, [t][4096]
__device__ __half g_kh[SLEN * KVDIM];   //  2 MB, [t][512]
__device__ __half g_vt[KVDIM * SLEN];   //  2 MB, transposed [d][t]
__device__ __half g_aoh[SLEN * QDIM];   // 16 MB, [t][4096]

// ---------------------------------------------------------------------------
// helpers
// ---------------------------------------------------------------------------
__device__ __forceinline__ uint32_t h2pack(float x, float y) {
    __half2 h = __floats2half2_rn(x, y);
    return *(uint32_t*)&h;
}

__device__ __forceinline__ void mma_f16(float* c, const uint32_t* a,
                                        uint32_t b0, uint32_t b1) {
    asm volatile(
        "mma.sync.aligned.m16n8k16.row.col.f32.f16.f16.f32 "
        "{%0,%1,%2,%3}, {%4,%5,%6,%7}, {%8,%9}, {%0,%1,%2,%3};"
        : "+f"(c[0]), "+f"(c[1]), "+f"(c[2]), "+f"(c[3])
        : "r"(a[0]), "r"(a[1]), "r"(a[2]), "r"(a[3]), "r"(b0), "r"(b1));
}

#define CP_ASYNC16(dst, src)                                             \
    asm volatile("cp.async.cg.shared.global [%0], [%1], 16;"             \
                 :: "r"(dst), "l"(src))
#define CP_COMMIT() asm volatile("cp.async.commit_group;")

__device__ __forceinline__ uint32_t smem_u32(const void* p) {
    return (uint32_t)__cvta_generic_to_shared(p);
}

// ============================================================================
// Fused QKV GEMM (fp32 in -> fp16 out). Tile 128x128, BK=32, 256 threads.
// blockIdx.x: [0,32) Q -> g_qh, [32,36) K -> g_kh, [36,40) V -> g_vt (transposed).
// smem pad 40 halves/row: fragment LDS bank = 4g+tg+20r pattern, conflict-free.
// Single __syncthreads per K-tile (double buffer).
// ============================================================================
#define GLD 40

__global__ __launch_bounds__(256) void qkv_gemm(
    const float* __restrict__ hs,
    const float* __restrict__ Wq, const float* __restrict__ bq,
    const float* __restrict__ Wk, const float* __restrict__ bk,
    const float* __restrict__ Wv, const float* __restrict__ bv)
{
    __shared__ __half Ah[2][128 * GLD];
    __shared__ __half Bh[2][128 * GLD];

    const int bx = blockIdx.x;
    const int mode = (bx < 32) ? 0 : ((bx < 36) ? 1 : 2);
    const float* W    = (mode == 0) ? Wq : ((mode == 1) ? Wk : Wv);
    const float* bias = (mode == 0) ? bq : ((mode == 1) ? bk : bv);
    const int n0 = ((mode == 0) ? bx : ((mode == 1) ? bx - 32 : bx - 36)) * 128;

    const int tid  = threadIdx.x;
    const int lane = tid & 31;
    const int w    = tid >> 5;
    const int wm   = (w & 3) * 32;
    const int wn   = (w >> 2) * 64;
    const int m0   = blockIdx.y * 128;
    const int g    = lane >> 2;
    const int tg   = lane & 3;

    float acc[2][8][4];
#pragma unroll
    for (int i = 0; i < 2; i++)
#pragma unroll
        for (int j = 0; j < 8; j++)
#pragma unroll
            for (int q = 0; q < 4; q++) acc[i][j][q] = 0.0f;

    const int lrow = tid >> 3;
    const int lc4  = tid & 7;

    float4 ra[4], rb[4];
    auto ldg_tile = [&](int k0) {
#pragma unroll
        for (int i = 0; i < 4; i++) {
            const int row = lrow + i * 32;
            ra[i] = *(const float4*)(hs + (size_t)(m0 + row) * HIDDEN + k0 + lc4 * 4);
            rb[i] = *(const float4*)(W + (size_t)(n0 + row) * HIDDEN + k0 + lc4 * 4);
        }
    };
    auto sts_tile = [&](int buf) {
#pragma unroll
        for (int i = 0; i < 4; i++) {
            const int row = lrow + i * 32;
            uint2 va, vb;
            va.x = h2pack(ra[i].x, ra[i].y);
            va.y = h2pack(ra[i].z, ra[i].w);
            vb.x = h2pack(rb[i].x, rb[i].y);
            vb.y = h2pack(rb[i].z, rb[i].w);
            *(uint2*)&Ah[buf][row * GLD + lc4 * 4] = va;
            *(uint2*)&Bh[buf][row * GLD + lc4 * 4] = vb;
        }
    };

    const int KT = HIDDEN / 32;
    ldg_tile(0);
    sts_tile(0);
    __syncthreads();

    int buf = 0;
    for (int t = 0; t < KT; t++) {
        if (t + 1 < KT) ldg_tile((t + 1) * 32);

        const __half* Ab = Ah[buf];
        const __half* Bb = Bh[buf];
#pragma unroll
        for (int kk = 0; kk < 2; kk++) {
            uint32_t a[2][4];
#pragma unroll
            for (int mi = 0; mi < 2; mi++) {
                const int r = wm + mi * 16 + g;
                const int c = kk * 16 + 2 * tg;
                a[mi][0] = *(const uint32_t*)&Ab[r * GLD + c];
                a[mi][1] = *(const uint32_t*)&Ab[(r + 8) * GLD + c];
                a[mi][2] = *(const uint32_t*)&Ab[r * GLD + c + 8];
                a[mi][3] = *(const uint32_t*)&Ab[(r + 8) * GLD + c + 8];
            }
#pragma unroll
            for (int nj = 0; nj < 8; nj++) {
                const int nr = wn + nj * 8 + g;
                const int c = kk * 16 + 2 * tg;
                const uint32_t b0 = *(const uint32_t*)&Bb[nr * GLD + c];
                const uint32_t b1 = *(const uint32_t*)&Bb[nr * GLD + c + 8];
                mma_f16(acc[0][nj], a[0], b0, b1);
                mma_f16(acc[1][nj], a[1], b0, b1);
            }
        }
        if (t + 1 < KT) sts_tile(buf ^ 1);
        __syncthreads();
        buf ^= 1;
    }

    // epilogue -> fp16 outputs
#pragma unroll
    for (int mi = 0; mi < 2; mi++) {
#pragma unroll
        for (int nj = 0; nj < 8; nj++) {
            const int col = n0 + wn + nj * 8 + 2 * tg;
            const int row = m0 + wm + mi * 16 + g;
            const float b0 = bias[col];
            const float b1 = bias[col + 1];
            const float v00 = acc[mi][nj][0] + b0, v01 = acc[mi][nj][1] + b1;
            const float v10 = acc[mi][nj][2] + b0, v11 = acc[mi][nj][3] + b1;
            if (mode == 0) {
                *(uint32_t*)&g_qh[(size_t)row * QDIM + col] = h2pack(v00, v01);
                *(uint32_t*)&g_qh[(size_t)(row + 8) * QDIM + col] = h2pack(v10, v11);
            } else if (mode == 1) {
                *(uint32_t*)&g_kh[(size_t)row * KVDIM + col] = h2pack(v00, v01);
                *(uint32_t*)&g_kh[(size_t)(row + 8) * KVDIM + col] = h2pack(v10, v11);
            } else {
                g_vt[(size_t)col * SLEN + row]           = __float2half_rn(v00);
                g_vt[(size_t)(col + 1) * SLEN + row]     = __float2half_rn(v01);
                g_vt[(size_t)col * SLEN + row + 8]       = __float2half_rn(v10);
                g_vt[(size_t)(col + 1) * SLEN + row + 8] = __float2half_rn(v11);
            }
        }
    }
}

// ============================================================================
// FP16 flash attention (causal, GQA 8:1). 128 threads, 4 warps, all compute.
// Inputs pre-converted fp16; V pre-transposed. cp.async double buffer.
// Warp w owns q-rows [w*16, w*16+16); P stays in registers (C-frag -> A-frag).
// smem pad 72 halves: fragment LDS conflict-free; 144B row stride keeps
// 16B cp.async alignment.
// ============================================================================
#define FLD 72

__global__ __launch_bounds__(128) void flash_f16(float* /*unused*/)
{
    __shared__ __half Qh[64 * FLD];
    __shared__ __half Kh[2][64 * FLD];
    __shared__ __half Vh[2][64 * FLD];   // [d][t]

    const int h    = blockIdx.y;
    const int qb   = blockIdx.x;
    const int kvh  = h >> 3;
    const int tid  = threadIdx.x;
    const int wid  = tid >> 5;
    const int lane = tid & 31;
    const int g    = lane >> 2;
    const int tg   = lane & 3;
    const int r0   = qb * 64;
    const int wr   = wid * 16;

    const int lr = tid >> 3;   // 0..15 base row, advance by 16
    const int lc = tid & 7;    // chunk 0..7

    auto issue_kv = [&](int j, int buf) {
        const int t0 = j * 64;
#pragma unroll
        for (int i = 0; i < 4; i++) {
            const int r = lr + i * 16;
            CP_ASYNC16(smem_u32(&Kh[buf][r * FLD + lc * 8]),
                       &g_kh[(size_t)(t0 + r) * KVDIM + kvh * HDIM + lc * 8]);
            CP_ASYNC16(smem_u32(&Vh[buf][r * FLD + lc * 8]),
                       &g_vt[(size_t)(kvh * HDIM + r) * SLEN + t0 + lc * 8]);
        }
        CP_COMMIT();
    };

    // prologue: Q + kv tile 0
#pragma unroll
    for (int i = 0; i < 4; i++) {
        const int r = lr + i * 16;
        CP_ASYNC16(smem_u32(&Qh[r * FLD + lc * 8]),
                   &g_qh[(size_t)(r0 + r) * QDIM + h * HDIM + lc * 8]);
    }
    CP_COMMIT();
    issue_kv(0, 0);
    asm volatile("cp.async.wait_group 0;");
    __syncthreads();

    uint32_t qf[4][4];
#pragma unroll
    for (int kk = 0; kk < 4; kk++) {
        const int c = kk * 16 + 2 * tg;
        qf[kk][0] = *(const uint32_t*)&Qh[(wr + g) * FLD + c];
        qf[kk][1] = *(const uint32_t*)&Qh[(wr + g + 8) * FLD + c];
        qf[kk][2] = *(const uint32_t*)&Qh[(wr + g) * FLD + c + 8];
        qf[kk][3] = *(const uint32_t*)&Qh[(wr + g + 8) * FLD + c + 8];
    }

    float o[8][4];
#pragma unroll
    for (int nj = 0; nj < 8; nj++)
#pragma unroll
        for (int c = 0; c < 4; c++) o[nj][c] = 0.0f;
    float m_lo = -1e30f, m_hi = -1e30f, l_lo = 0.0f, l_hi = 0.0f;

    int buf = 0;
    for (int j = 0; j <= qb; j++) {
        if (j < qb) {
            issue_kv(j + 1, buf ^ 1);
            asm volatile("cp.async.wait_group 1;");
        } else {
            asm volatile("cp.async.wait_group 0;");
        }
        __syncthreads();

        const __half* Kb = Kh[buf];
        const __half* Vb = Vh[buf];

        // ---- S = Q . K^T ----
        float s[8][4];
#pragma unroll
        for (int nj = 0; nj < 8; nj++)
#pragma unroll
            for (int c = 0; c < 4; c++) s[nj][c] = 0.0f;
#pragma unroll
        for (int kk = 0; kk < 4; kk++) {
            const int c = kk * 16 + 2 * tg;
#pragma unroll
            for (int nj = 0; nj < 8; nj++) {
                const uint32_t b0 = *(const uint32_t*)&Kb[(nj * 8 + g) * FLD + c];
                const uint32_t b1 = *(const uint32_t*)&Kb[(nj * 8 + g) * FLD + c + 8];
                mma_f16(s[nj], qf[kk], b0, b1);
            }
        }

        // ---- scale + causal mask ----
        const int t0 = j * 64;
        const bool diag = (j == qb);
        const int row_lo = r0 + wr + g;
        const int row_hi = row_lo + 8;
#pragma unroll
        for (int nj = 0; nj < 8; nj++) {
            const int cb = t0 + nj * 8 + 2 * tg;
            float v0 = s[nj][0] * 0.125f;
            float v1 = s[nj][1] * 0.125f;
            float v2 = s[nj][2] * 0.125f;
            float v3 = s[nj][3] * 0.125f;
            if (diag) {
                if (cb     > row_lo) v0 = -1e30f;
                if (cb + 1 > row_lo) v1 = -1e30f;
                if (cb     > row_hi) v2 = -1e30f;
                if (cb + 1 > row_hi) v3 = -1e30f;
            }
            s[nj][0] = v0; s[nj][1] = v1; s[nj][2] = v2; s[nj][3] = v3;
        }

        // ---- online softmax ----
        float mx_lo = -1e30f, mx_hi = -1e30f;
#pragma unroll
        for (int nj = 0; nj < 8; nj++) {
            mx_lo = fmaxf(mx_lo, fmaxf(s[nj][0], s[nj][1]));
            mx_hi = fmaxf(mx_hi, fmaxf(s[nj][2], s[nj][3]));
        }
        mx_lo = fmaxf(mx_lo, __shfl_xor_sync(0xffffffffu, mx_lo, 1));
        mx_lo = fmaxf(mx_lo, __shfl_xor_sync(0xffffffffu, mx_lo, 2));
        mx_hi = fmaxf(mx_hi, __shfl_xor_sync(0xffffffffu, mx_hi, 1));
        mx_hi = fmaxf(mx_hi, __shfl_xor_sync(0xffffffffu, mx_hi, 2));

        const float mn_lo = fmaxf(m_lo, mx_lo);
        const float mn_hi = fmaxf(m_hi, mx_hi);
        const float corr_lo = __expf(m_lo - mn_lo);
        const float corr_hi = __expf(m_hi - mn_hi);

        float sum_lo = 0.0f, sum_hi = 0.0f;
#pragma unroll
        for (int nj = 0; nj < 8; nj++) {
            s[nj][0] = __expf(s[nj][0] - mn_lo);
            s[nj][1] = __expf(s[nj][1] - mn_lo);
            s[nj][2] = __expf(s[nj][2] - mn_hi);
            s[nj][3] = __expf(s[nj][3] - mn_hi);
            sum_lo += s[nj][0] + s[nj][1];
            sum_hi += s[nj][2] + s[nj][3];
        }
        sum_lo += __shfl_xor_sync(0xffffffffu, sum_lo, 1);
        sum_lo += __shfl_xor_sync(0xffffffffu, sum_lo, 2);
        sum_hi += __shfl_xor_sync(0xffffffffu, sum_hi, 1);
        sum_hi += __shfl_xor_sync(0xffffffffu, sum_hi, 2);

        l_lo = l_lo * corr_lo + sum_lo;
        l_hi = l_hi * corr_hi + sum_hi;
        m_lo = mn_lo;
        m_hi = mn_hi;
#pragma unroll
        for (int nj = 0; nj < 8; nj++) {
            o[nj][0] *= corr_lo; o[nj][1] *= corr_lo;
            o[nj][2] *= corr_hi; o[nj][3] *= corr_hi;
        }

        // ---- O += P . V (P repacked in registers) ----
#pragma unroll
        for (int kk = 0; kk < 4; kk++) {
            uint32_t pa[4];
            pa[0] = h2pack(s[2 * kk][0],     s[2 * kk][1]);
            pa[1] = h2pack(s[2 * kk][2],     s[2 * kk][3]);
            pa[2] = h2pack(s[2 * kk + 1][0], s[2 * kk + 1][1]);
            pa[3] = h2pack(s[2 * kk + 1][2], s[2 * kk + 1][3]);
            const int c = kk * 16 + 2 * tg;
#pragma unroll
            for (int nj = 0; nj < 8; nj++) {
                const uint32_t b0 = *(const uint32_t*)&Vb[(nj * 8 + g) * FLD + c];
                const uint32_t b1 = *(const uint32_t*)&Vb[(nj * 8 + g) * FLD + c + 8];
                mma_f16(o[nj], pa, b0, b1);
            }
        }
        __syncthreads();
        buf ^= 1;
    }

    // ---- write normalized fp16 output ----
    const float inv_lo = 1.0f / l_lo;
    const float inv_hi = 1.0f / l_hi;
#pragma unroll
    for (int nj = 0; nj < 8; nj++) {
        const int col = h * HDIM + nj * 8 + 2 * tg;
        *(uint32_t*)&g_aoh[(size_t)(r0 + wr + g) * QDIM + col] =
            h2pack(o[nj][0] * inv_lo, o[nj][1] * inv_lo);
        *(uint32_t*)&g_aoh[(size_t)(r0 + wr + g + 8) * QDIM + col] =
            h2pack(o[nj][2] * inv_hi, o[nj][3] * inv_hi);
    }
}

// ============================================================================
// Output projection: out[m][n] = sum_k g_aoh[m][k]*Wo[n][k] + bo[n], fp32 out.
// A operand already fp16 (LDG.128 + STS.64, no CVT); B fp32 -> fp16 at STS.
// ============================================================================
__global__ __launch_bounds__(256) void wo_gemm(
    const float* __restrict__ Wo, const float* __restrict__ bo,
    float* __restrict__ C)
{
    __shared__ __half Ah[2][128 * GLD];
    __shared__ __half Bh[2][128 * GLD];

    const int tid  = threadIdx.x;
    const int lane = tid & 31;
    const int w    = tid >> 5;
    const int wm   = (w & 3) * 32;
    const int wn   = (w >> 2) * 64;
    const int m0   = blockIdx.y * 128;
    const int n0   = blockIdx.x * 128;
    const int g    = lane >> 2;
    const int tg   = lane & 3;

    float acc[2][8][4];
#pragma unroll
    for (int i = 0; i < 2; i++)
#pragma unroll
        for (int j = 0; j < 8; j++)
#pragma unroll
            for (int q = 0; q < 4; q++) acc[i][j][q] = 0.0f;

    // A loader: 2 chunks (idx = tid + i*256, row = idx>>2, c = idx&3)
    const int arow = tid >> 2;
    const int ac   = tid & 3;
    // B loader: 4 float4 (row = idx>>3, c = idx&7)
    const int brow = tid >> 3;
    const int bc   = tid & 7;

    uint4 ra[2];
    float4 rb[4];
    auto ldg_tile = [&](int k0) {
#pragma unroll
        for (int i = 0; i < 2; i++) {
            const int row = arow + i * 64;
            ra[i] = *(const uint4*)&g_aoh[(size_t)(m0 + row) * QDIM + k0 + ac * 8];
        }
#pragma unroll
        for (int i = 0; i < 4; i++) {
            const int nrow = n0 + brow + i * 32;
            rb[i] = *(const float4*)(Wo + (size_t)(nrow < HIDDEN ? nrow : 0) * QDIM + k0 + bc * 4);
        }
    };
    auto sts_tile = [&](int buf) {
#pragma unroll
        for (int i = 0; i < 2; i++) {
            const int row = arow + i * 64;
            *(uint2*)&Ah[buf][row * GLD + ac * 8]     = make_uint2(ra[i].x, ra[i].y);
            *(uint2*)&Ah[buf][row * GLD + ac * 8 + 4] = make_uint2(ra[i].z, ra[i].w);
        }
#pragma unroll
        for (int i = 0; i < 4; i++) {
            const int row = brow + i * 32;
            uint2 vb;
            vb.x = h2pack(rb[i].x, rb[i].y);
            vb.y = h2pack(rb[i].z, rb[i].w);
            *(uint2*)&Bh[buf][row * GLD + bc * 4] = vb;
        }
    };

    const int KT = QDIM / 32;
    ldg_tile(0);
    sts_tile(0);
    __syncthreads();

    int buf = 0;
    for (int t = 0; t < KT; t++) {
        if (t + 1 < KT) ldg_tile((t + 1) * 32);

        const __half* Ab = Ah[buf];
        const __half* Bb = Bh[buf];
#pragma unroll
        for (int kk = 0; kk < 2; kk++) {
            uint32_t a[2][4];
#pragma unroll
            for (int mi = 0; mi < 2; mi++) {
                const int r = wm + mi * 16 + g;
                const int c = kk * 16 + 2 * tg;
                a[mi][0] = *(const uint32_t*)&Ab[r * GLD + c];
                a[mi][1] = *(const uint32_t*)&Ab[(r + 8) * GLD + c];
                a[mi][2] = *(const uint32_t*)&Ab[r * GLD + c + 8];
                a[mi][3] = *(const uint32_t*)&Ab[(r + 8) * GLD + c + 8];
            }
#pragma unroll
            for (int nj = 0; nj < 8; nj++) {
                const int nr = wn + nj * 8 + g;
                const int c = kk * 16 + 2 * tg;
                const uint32_t b0 = *(const uint32_t*)&Bb[nr * GLD + c];
                const uint32_t b1 = *(const uint32_t*)&Bb[nr * GLD + c + 8];
                mma_f16(acc[0][nj], a[0], b0, b1);
                mma_f16(acc[1][nj], a[1], b0, b1);
            }
        }
        if (t + 1 < KT) sts_tile(buf ^ 1);
        __syncthreads();
        buf ^= 1;
    }

#pragma unroll
    for (int mi = 0; mi < 2; mi++) {
#pragma unroll
        for (int nj = 0; nj < 8; nj++) {
            const int col = n0 + wn + nj * 8 + 2 * tg;
            if (col < HIDDEN) {
                const float b0 = bo[col];
                const float b1 = bo[col + 1];
                const int row = m0 + wm + mi * 16 + g;
                *(float2*)(C + (size_t)row * HIDDEN + col) =
                    make_float2(acc[mi][nj][0] + b0, acc[mi][nj][1] + b1);
                *(float2*)(C + (size_t)(row + 8) * HIDDEN + col) =
                    make_float2(acc[mi][nj][2] + b0, acc[mi][nj][3] + b1);
            }
        }
    }
}

// ============================================================================
// launch
// ============================================================================
extern "C" void kernel_launch(void* const* d_in, const int* in_sizes, int n_in,
                              void* d_out, int out_size)
{
    (void)in_sizes; (void)n_in; (void)out_size;
    const float* hs = (const float*)d_in[0];
    const float* Wq = (const float*)d_in[2];
    const float* bq = (const float*)d_in[3];
    const float* Wk = (const float*)d_in[4];
    const float* bk = (const float*)d_in[5];
    const float* Wv = (const float*)d_in[6];
    const float* bv = (const float*)d_in[7];
    const float* Wo = (const float*)d_in[8];
    const float* bo = (const float*)d_in[9];
    float* out = (float*)d_out;

    qkv_gemm<<<dim3(40, SLEN / 128), 256>>>(hs, Wq, bq, Wk, bk, Wv, bv);
    flash_f16<<<dim3(SLEN / 64, NHEADS), 128>>>(out);
    wo_gemm<<<dim3((HIDDEN + 127) / 128, SLEN / 128), 256>>>(Wo, bo, out);
}

// round 8
// speedup vs baseline: 8.4314x; 1.5705x over previous
#include <cuda_runtime.h>
#include <cuda_fp16.h>
#include <math.h>
#include <stdint.h>

#define SLEN 2048
#define HIDDEN 2880
#define NHEADS 64
#define NKV 8
#define HDIM 64
#define QDIM (NHEADS * HDIM)   /* 4096 */
#define KVDIM (NKV * HDIM)     /* 512  */

// -------------------- scratch (static device globals; no allocation) ---------
__device__ __half g_hsh[SLEN * HIDDEN];   // hidden_states fp16
__device__ __half g_wqh[QDIM * HIDDEN];   // Wq fp16
__device__ __half g_wkh[KVDIM * HIDDEN];  // Wk fp16
__device__ __half g_wvh[KVDIM * HIDDEN];  // Wv fp16
__device__ __half g_woh[HIDDEN * QDIM];   // Wo fp16
__device__ __half g_qh[SLEN * QDIM];      // Q  [t][4096]
__device__ __half g_kh[SLEN * KVDIM];     // K  [t][512]
__device__ __half g_vt[KVDIM * SLEN];     // V transposed [d][t]
__device__ __half g_aoh[SLEN * QDIM];     // attn out [t][4096]

// ---------------------------------------------------------------------------
// helpers
// ---------------------------------------------------------------------------
__device__ __forceinline__ uint32_t h2pack(float x, float y) {
    __half2 h = __floats2half2_rn(x, y);
    return *(uint32_t*)&h;
}

__device__ __forceinline__ void mma_f16(float* c, const uint32_t* a,
                                        uint32_t b0, uint32_t b1) {
    asm volatile(
        "mma.sync.aligned.m16n8k16.row.col.f32.f16.f16.f32 "
        "{%0,%1,%2,%3}, {%4,%5,%6,%7}, {%8,%9}, {%0,%1,%2,%3};"
        : "+f"(c[0]), "+f"(c[1]), "+f"(c[2]), "+f"(c[3])
        : "r"(a[0]), "r"(a[1]), "r"(a[2]), "r"(a[3]), "r"(b0), "r"(b1));
}

__device__ __forceinline__ void ldmx4(uint32_t& r0, uint32_t& r1,
                                      uint32_t& r2, uint32_t& r3,
                                      uint32_t addr) {
    asm volatile("ldmatrix.sync.aligned.m8n8.x4.shared.b16 {%0,%1,%2,%3}, [%4];"
                 : "=r"(r0), "=r"(r1), "=r"(r2), "=r"(r3) : "r"(addr));
}

#define CP_ASYNC16(dst, src)                                             \
    asm volatile("cp.async.cg.shared.global [%0], [%1], 16;"             \
                 :: "r"(dst), "l"(src))
#define CP_COMMIT() asm volatile("cp.async.commit_group;")
#define CP_WAIT0() asm volatile("cp.async.wait_group 0;")
#define CP_WAIT1() asm volatile("cp.async.wait_group 1;")
#define CP_WAIT2() asm volatile("cp.async.wait_group 2;")

__device__ __forceinline__ uint32_t smem_u32(const void* p) {
    return (uint32_t)__cvta_generic_to_shared(p);
}

// ============================================================================
// fp32 -> fp16 converter (grid-stride, float4 -> 4 halves)
// ============================================================================
__global__ void cvt_f16(const float4* __restrict__ src, uint2* __restrict__ dst,
                        int n4)
{
    int i = blockIdx.x * blockDim.x + threadIdx.x;
    const int stride = gridDim.x * blockDim.x;
    for (; i < n4; i += stride) {
        float4 v = src[i];
        dst[i] = make_uint2(h2pack(v.x, v.y), h2pack(v.z, v.w));
    }
}

// ============================================================================
// fp16 GEMM: tile 128x128, BK=32, 4-stage cp.async pipeline, 256 threads,
// 8 warps each 32x64, ldmatrix fragment loads. smem stride GLD=40 halves.
// ============================================================================
#define GLD 40
#define STG_H (128 * GLD)             /* halves per operand per stage */
#define GEMM_SMEM (4 * 2 * STG_H * 2) /* 81920 bytes */

// ============================================================================
// Fused QKV GEMM: all-fp16 inputs, fp16 outputs (V transposed).
// blockIdx.x: [0,32) Q, [32,36) K, [36,40) V.
// ============================================================================
__global__ __launch_bounds__(256, 2) void qkv_gemm(
    const float* __restrict__ bq, const float* __restrict__ bk,
    const float* __restrict__ bv)
{
    extern __shared__ __half gsm[];

    const int bx = blockIdx.x;
    const int mode = (bx < 32) ? 0 : ((bx < 36) ? 1 : 2);
    const __half* Bg = (mode == 0) ? g_wqh : ((mode == 1) ? g_wkh : g_wvh);
    const float* bias = (mode == 0) ? bq : ((mode == 1) ? bk : bv);
    const int n0 = ((mode == 0) ? bx : ((mode == 1) ? bx - 32 : bx - 36)) * 128;

    const int tid  = threadIdx.x;
    const int lane = tid & 31;
    const int w    = tid >> 5;
    const int wm   = (w & 3) * 32;
    const int wn   = (w >> 2) * 64;
    const int m0   = blockIdx.y * 128;
    const int g    = lane >> 2;
    const int tg   = lane & 3;
    const int l8   = lane & 7;

    const int aoff = (wm + ((lane >> 3) & 1) * 8 + l8) * GLD + (lane >> 4) * 8;
    const int boff = (wn + (lane >> 4) * 8 + l8) * GLD + ((lane >> 3) & 1) * 8;

    float acc[2][8][4];
#pragma unroll
    for (int i = 0; i < 2; i++)
#pragma unroll
        for (int j = 0; j < 8; j++)
#pragma unroll
            for (int q = 0; q < 4; q++) acc[i][j][q] = 0.0f;

    // loader: BK=32 halves = 64B = 4 chunks; 128 rows x 4 chunks = 512 items
    const int lrow = tid >> 2;   // 0..63
    const int lch  = tid & 3;

    auto issue = [&](int t) {
        const int s = t & 3;
        __half* Ab = gsm + s * (2 * STG_H);
        __half* Bb = Ab + STG_H;
        const int k0 = t * 32;
#pragma unroll
        for (int i = 0; i < 2; i++) {
            const int r = lrow + i * 64;
            CP_ASYNC16(smem_u32(&Ab[r * GLD + lch * 8]),
                       g_hsh + (size_t)(m0 + r) * HIDDEN + k0 + lch * 8);
            CP_ASYNC16(smem_u32(&Bb[r * GLD + lch * 8]),
                       Bg + (size_t)(n0 + r) * HIDDEN + k0 + lch * 8);
        }
        CP_COMMIT();
    };

    const int KT = HIDDEN / 32;  // 90
    issue(0); issue(1); issue(2);

    for (int t = 0; t < KT; t++) {
        const int rem = KT - 1 - t;
        if (rem >= 2) CP_WAIT2();
        else if (rem == 1) CP_WAIT1();
        else CP_WAIT0();
        __syncthreads();

        const int s = t & 3;
        const __half* Ab = gsm + s * (2 * STG_H);
        const __half* Bb = Ab + STG_H;
        const uint32_t abase = smem_u32(&Ab[aoff]);
        const uint32_t bbase = smem_u32(&Bb[boff]);

#pragma unroll
        for (int kk = 0; kk < 2; kk++) {
            uint32_t a[2][4];
#pragma unroll
            for (int mi = 0; mi < 2; mi++)
                ldmx4(a[mi][0], a[mi][1], a[mi][2], a[mi][3],
                      abase + (mi * 16 * GLD + kk * 16) * 2);
#pragma unroll
            for (int p = 0; p < 4; p++) {
                uint32_t b00, b01, b10, b11;
                ldmx4(b00, b01, b10, b11,
                      bbase + (p * 16 * GLD + kk * 16) * 2);
                mma_f16(acc[0][2 * p],     a[0], b00, b01);
                mma_f16(acc[0][2 * p + 1], a[0], b10, b11);
                mma_f16(acc[1][2 * p],     a[1], b00, b01);
                mma_f16(acc[1][2 * p + 1], a[1], b10, b11);
            }
        }
        if (t + 3 < KT) issue(t + 3);
    }

    // epilogue -> fp16 outputs
#pragma unroll
    for (int mi = 0; mi < 2; mi++) {
#pragma unroll
        for (int nj = 0; nj < 8; nj++) {
            const int col = n0 + wn + nj * 8 + 2 * tg;
            const int row = m0 + wm + mi * 16 + g;
            const float b0 = bias[col];
            const float b1 = bias[col + 1];
            const float v00 = acc[mi][nj][0] + b0, v01 = acc[mi][nj][1] + b1;
            const float v10 = acc[mi][nj][2] + b0, v11 = acc[mi][nj][3] + b1;
            if (mode == 0) {
                *(uint32_t*)&g_qh[(size_t)row * QDIM + col] = h2pack(v00, v01);
                *(uint32_t*)&g_qh[(size_t)(row + 8) * QDIM + col] = h2pack(v10, v11);
            } else if (mode == 1) {
                *(uint32_t*)&g_kh[(size_t)row * KVDIM + col] = h2pack(v00, v01);
                *(uint32_t*)&g_kh[(size_t)(row + 8) * KVDIM + col] = h2pack(v10, v11);
            } else {
                g_vt[(size_t)col * SLEN + row]           = __float2half_rn(v00);
                g_vt[(size_t)(col + 1) * SLEN + row]     = __float2half_rn(v01);
                g_vt[(size_t)col * SLEN + row + 8]       = __float2half_rn(v10);
                g_vt[(size_t)(col + 1) * SLEN + row + 8] = __float2half_rn(v11);
            }
        }
    }
}

// ============================================================================
// Output projection: fp16 A (g_aoh) x fp16 B (g_woh) -> fp32 out + bias.
// ============================================================================
__global__ __launch_bounds__(256, 2) void wo_gemm(
    const float* __restrict__ bo, float* __restrict__ C)
{
    extern __shared__ __half gsm[];

    const int tid  = threadIdx.x;
    const int lane = tid & 31;
    const int w    = tid >> 5;
    const int wm   = (w & 3) * 32;
    const int wn   = (w >> 2) * 64;
    const int m0   = blockIdx.y * 128;
    const int n0   = blockIdx.x * 128;
    const int g    = lane >> 2;
    const int tg   = lane & 3;
    const int l8   = lane & 7;

    const int aoff = (wm + ((lane >> 3) & 1) * 8 + l8) * GLD + (lane >> 4) * 8;
    const int boff = (wn + (lane >> 4) * 8 + l8) * GLD + ((lane >> 3) & 1) * 8;

    float acc[2][8][4];
#pragma unroll
    for (int i = 0; i < 2; i++)
#pragma unroll
        for (int j = 0; j < 8; j++)
#pragma unroll
            for (int q = 0; q < 4; q++) acc[i][j][q] = 0.0f;

    const int lrow = tid >> 2;
    const int lch  = tid & 3;

    auto issue = [&](int t) {
        const int s = t & 3;
        __half* Ab = gsm + s * (2 * STG_H);
        __half* Bb = Ab + STG_H;
        const int k0 = t * 32;
#pragma unroll
        for (int i = 0; i < 2; i++) {
            const int r = lrow + i * 64;
            CP_ASYNC16(smem_u32(&Ab[r * GLD + lch * 8]),
                       g_aoh + (size_t)(m0 + r) * QDIM + k0 + lch * 8);
            const int nrow = n0 + r;
            CP_ASYNC16(smem_u32(&Bb[r * GLD + lch * 8]),
                       g_woh + (size_t)(nrow < HIDDEN ? nrow : 0) * QDIM + k0 + lch * 8);
        }
        CP_COMMIT();
    };

    const int KT = QDIM / 32;  // 128
    issue(0); issue(1); issue(2);

    for (int t = 0; t < KT; t++) {
        const int rem = KT - 1 - t;
        if (rem >= 2) CP_WAIT2();
        else if (rem == 1) CP_WAIT1();
        else CP_WAIT0();
        __syncthreads();

        const int s = t & 3;
        const __half* Ab = gsm + s * (2 * STG_H);
        const __half* Bb = Ab + STG_H;
        const uint32_t abase = smem_u32(&Ab[aoff]);
        const uint32_t bbase = smem_u32(&Bb[boff]);

#pragma unroll
        for (int kk = 0; kk < 2; kk++) {
            uint32_t a[2][4];
#pragma unroll
            for (int mi = 0; mi < 2; mi++)
                ldmx4(a[mi][0], a[mi][1], a[mi][2], a[mi][3],
                      abase + (mi * 16 * GLD + kk * 16) * 2);
#pragma unroll
            for (int p = 0; p < 4; p++) {
                uint32_t b00, b01, b10, b11;
                ldmx4(b00, b01, b10, b11,
                      bbase + (p * 16 * GLD + kk * 16) * 2);
                mma_f16(acc[0][2 * p],     a[0], b00, b01);
                mma_f16(acc[0][2 * p + 1], a[0], b10, b11);
                mma_f16(acc[1][2 * p],     a[1], b00, b01);
                mma_f16(acc[1][2 * p + 1], a[1], b10, b11);
            }
        }
        if (t + 3 < KT) issue(t + 3);
    }

#pragma unroll
    for (int mi = 0; mi < 2; mi++) {
#pragma unroll
        for (int nj = 0; nj < 8; nj++) {
            const int col = n0 + wn + nj * 8 + 2 * tg;
            if (col < HIDDEN) {
                const float b0 = bo[col];
                const float b1 = bo[col + 1];
                const int row = m0 + wm + mi * 16 + g;
                *(float2*)(C + (size_t)row * HIDDEN + col) =
                    make_float2(acc[mi][nj][0] + b0, acc[mi][nj][1] + b1);
                *(float2*)(C + (size_t)(row + 8) * HIDDEN + col) =
                    make_float2(acc[mi][nj][2] + b0, acc[mi][nj][3] + b1);
            }
        }
    }
}

// ============================================================================
// FP16 flash attention, BM=128, 8 warps (all compute), causal GQA 8:1.
// Heavy-qb-first. KV tile 64, double-buffered cp.async. Q staged through the
// KV buffers then lifted to registers. Warps skip fully-masked tiles.
// Row = 64 halves = 128 B = 8 x 16B chunks. Pad FLD=72 halves (144 B).
// ============================================================================
#define FLD 72

__global__ __launch_bounds__(256, 2) void flash_f16()
{
    __shared__ __half Kh[2][64 * FLD];
    __shared__ __half Vh[2][64 * FLD];

    const int h    = blockIdx.y;
    const int qb   = gridDim.x - 1 - blockIdx.x;   // heavy first
    const int kvh  = h >> 3;
    const int tid  = threadIdx.x;
    const int wid  = tid >> 5;
    const int lane = tid & 31;
    const int g    = lane >> 2;
    const int tg   = lane & 3;
    const int l8   = lane & 7;
    const int r0   = qb * 128;
    const int wr   = wid * 16;

    // ldmatrix per-lane offsets (halves)
    const int qoff  = ((wr & 63) + ((lane >> 3) & 1) * 8 + l8) * FLD + (lane >> 4) * 8;
    const int kvoff = ((lane >> 4) * 8 + l8) * FLD + ((lane >> 3) & 1) * 8;

    // ---- stage Q (128 rows x 8 chunks = 1024 items) through Kh[0]+Vh[0] ----
#pragma unroll
    for (int i = 0; i < 4; i++) {
        const int idx = tid + i * 256;
        const int r = idx >> 3, ch = idx & 7;
        __half* dst = (r < 64) ? &Kh[0][r * FLD + ch * 8]
                               : &Vh[0][(r - 64) * FLD + ch * 8];
        CP_ASYNC16(smem_u32(dst),
                   g_qh + (size_t)(r0 + r) * QDIM + h * HDIM + ch * 8);
    }
    CP_COMMIT();
    CP_WAIT0();
    __syncthreads();

    uint32_t qf[4][4];
    {
        const __half* Qb = (wid < 4) ? &Kh[0][0] : &Vh[0][0];
        const uint32_t qbase = smem_u32(&Qb[qoff]);
#pragma unroll
        for (int kk = 0; kk < 4; kk++)
            ldmx4(qf[kk][0], qf[kk][1], qf[kk][2], qf[kk][3],
                  qbase + kk * 16 * 2);
    }
    __syncthreads();

    // KV tile: 64 rows x 8 chunks = 512 items, 2 per thread
    const int lr = tid >> 3;   // 0..31 base row, advance by 32
    const int lc = tid & 7;

    auto issue_kv = [&](int j, int buf) {
        const int t0 = j * 64;
#pragma unroll
        for (int i = 0; i < 2; i++) {
            const int r = lr + i * 32;
            CP_ASYNC16(smem_u32(&Kh[buf][r * FLD + lc * 8]),
                       g_kh + (size_t)(t0 + r) * KVDIM + kvh * HDIM + lc * 8);
            CP_ASYNC16(smem_u32(&Vh[buf][r * FLD + lc * 8]),
                       g_vt + (size_t)(kvh * HDIM + r) * SLEN + t0 + lc * 8);
        }
        CP_COMMIT();
    };

    float o[8][4];
#pragma unroll
    for (int nj = 0; nj < 8; nj++)
#pragma unroll
        for (int c = 0; c < 4; c++) o[nj][c] = 0.0f;
    float m_lo = -1e30f, m_hi = -1e30f, l_lo = 0.0f, l_hi = 0.0f;

    const int jmax = 2 * qb + 1;
    issue_kv(0, 0);
    int buf = 0;

    for (int j = 0; j <= jmax; j++) {
        if (j < jmax) {
            issue_kv(j + 1, buf ^ 1);
            CP_WAIT1();
        } else {
            CP_WAIT0();
        }
        __syncthreads();

        const int t0 = j * 64;
        if (t0 <= r0 + wr + 15) {   // tile not fully masked for this warp
            const uint32_t kbase = smem_u32(&Kh[buf][kvoff]);
            const uint32_t vbase = smem_u32(&Vh[buf][kvoff]);

            // ---- S = Q . K^T ----
            float s[8][4];
#pragma unroll
            for (int nj = 0; nj < 8; nj++)
#pragma unroll
                for (int c = 0; c < 4; c++) s[nj][c] = 0.0f;
#pragma unroll
            for (int kk = 0; kk < 4; kk++) {
#pragma unroll
                for (int p = 0; p < 4; p++) {
                    uint32_t b00, b01, b10, b11;
                    ldmx4(b00, b01, b10, b11,
                          kbase + (p * 16 * FLD + kk * 16) * 2);
                    mma_f16(s[2 * p],     qf[kk], b00, b01);
                    mma_f16(s[2 * p + 1], qf[kk], b10, b11);
                }
            }

            // ---- scale + causal mask ----
            const bool diag = (t0 + 63 > r0 + wr);
            const int row_lo = r0 + wr + g;
            const int row_hi = row_lo + 8;
#pragma unroll
            for (int nj = 0; nj < 8; nj++) {
                const int cb = t0 + nj * 8 + 2 * tg;
                float v0 = s[nj][0] * 0.125f;
                float v1 = s[nj][1] * 0.125f;
                float v2 = s[nj][2] * 0.125f;
                float v3 = s[nj][3] * 0.125f;
                if (diag) {
                    if (cb     > row_lo) v0 = -1e30f;
                    if (cb + 1 > row_lo) v1 = -1e30f;
                    if (cb     > row_hi) v2 = -1e30f;
                    if (cb + 1 > row_hi) v3 = -1e30f;
                }
                s[nj][0] = v0; s[nj][1] = v1; s[nj][2] = v2; s[nj][3] = v3;
            }

            // ---- online softmax ----
            float mx_lo = -1e30f, mx_hi = -1e30f;
#pragma unroll
            for (int nj = 0; nj < 8; nj++) {
                mx_lo = fmaxf(mx_lo, fmaxf(s[nj][0], s[nj][1]));
                mx_hi = fmaxf(mx_hi, fmaxf(s[nj][2], s[nj][3]));
            }
            mx_lo = fmaxf(mx_lo, __shfl_xor_sync(0xffffffffu, mx_lo, 1));
            mx_lo = fmaxf(mx_lo, __shfl_xor_sync(0xffffffffu, mx_lo, 2));
            mx_hi = fmaxf(mx_hi, __shfl_xor_sync(0xffffffffu, mx_hi, 1));
            mx_hi = fmaxf(mx_hi, __shfl_xor_sync(0xffffffffu, mx_hi, 2));

            const float mn_lo = fmaxf(m_lo, mx_lo);
            const float mn_hi = fmaxf(m_hi, mx_hi);
            const float corr_lo = __expf(m_lo - mn_lo);
            const float corr_hi = __expf(m_hi - mn_hi);

            float sum_lo = 0.0f, sum_hi = 0.0f;
#pragma unroll
            for (int nj = 0; nj < 8; nj++) {
                s[nj][0] = __expf(s[nj][0] - mn_lo);
                s[nj][1] = __expf(s[nj][1] - mn_lo);
                s[nj][2] = __expf(s[nj][2] - mn_hi);
                s[nj][3] = __expf(s[nj][3] - mn_hi);
                sum_lo += s[nj][0] + s[nj][1];
                sum_hi += s[nj][2] + s[nj][3];
            }
            sum_lo += __shfl_xor_sync(0xffffffffu, sum_lo, 1);
            sum_lo += __shfl_xor_sync(0xffffffffu, sum_lo, 2);
            sum_hi += __shfl_xor_sync(0xffffffffu, sum_hi, 1);
            sum_hi += __shfl_xor_sync(0xffffffffu, sum_hi, 2);

            l_lo = l_lo * corr_lo + sum_lo;
            l_hi = l_hi * corr_hi + sum_hi;
            m_lo = mn_lo;
            m_hi = mn_hi;
#pragma unroll
            for (int nj = 0; nj < 8; nj++) {
                o[nj][0] *= corr_lo; o[nj][1] *= corr_lo;
                o[nj][2] *= corr_hi; o[nj][3] *= corr_hi;
            }

            // ---- O += P . V ----
#pragma unroll
            for (int kk = 0; kk < 4; kk++) {
                uint32_t pa[4];
                pa[0] = h2pack(s[2 * kk][0],     s[2 * kk][1]);
                pa[1] = h2pack(s[2 * kk][2],     s[2 * kk][3]);
                pa[2] = h2pack(s[2 * kk + 1][0], s[2 * kk + 1][1]);
                pa[3] = h2pack(s[2 * kk + 1][2], s[2 * kk + 1][3]);
#pragma unroll
                for (int p = 0; p < 4; p++) {
                    uint32_t b00, b01, b10, b11;
                    ldmx4(b00, b01, b10, b11,
                          vbase + (p * 16 * FLD + kk * 16) * 2);
                    mma_f16(o[2 * p],     pa, b00, b01);
                    mma_f16(o[2 * p + 1], pa, b10, b11);
                }
            }
        }
        __syncthreads();
        buf ^= 1;
    }

    // ---- write normalized fp16 output ----
    const float inv_lo = 1.0f / l_lo;
    const float inv_hi = 1.0f / l_hi;
#pragma unroll
    for (int nj = 0; nj < 8; nj++) {
        const int col = h * HDIM + nj * 8 + 2 * tg;
        *(uint32_t*)&g_aoh[(size_t)(r0 + wr + g) * QDIM + col] =
            h2pack(o[nj][0] * inv_lo, o[nj][1] * inv_lo);
        *(uint32_t*)&g_aoh[(size_t)(r0 + wr + g + 8) * QDIM + col] =
            h2pack(o[nj][2] * inv_hi, o[nj][3] * inv_hi);
    }
}

// ============================================================================
// launch
// ============================================================================
extern "C" void kernel_launch(void* const* d_in, const int* in_sizes, int n_in,
                              void* d_out, int out_size)
{
    (void)in_sizes; (void)n_in; (void)out_size;
    const float* hs = (const float*)d_in[0];
    const float* Wq = (const float*)d_in[2];
    const float* bq = (const float*)d_in[3];
    const float* Wk = (const float*)d_in[4];
    const float* bk = (const float*)d_in[5];
    const float* Wv = (const float*)d_in[6];
    const float* bv = (const float*)d_in[7];
    const float* Wo = (const float*)d_in[8];
    const float* bo = (const float*)d_in[9];
    float* out = (float*)d_out;

    __half *hsh, *wqh, *wkh, *wvh, *woh;
    cudaGetSymbolAddress((void**)&hsh, g_hsh);
    cudaGetSymbolAddress((void**)&wqh, g_wqh);
    cudaGetSymbolAddress((void**)&wkh, g_wkh);
    cudaGetSymbolAddress((void**)&wvh, g_wvh);
    cudaGetSymbolAddress((void**)&woh, g_woh);

    static bool attr_set = false;
    if (!attr_set) {
        cudaFuncSetAttribute(qkv_gemm,
                             cudaFuncAttributeMaxDynamicSharedMemorySize, GEMM_SMEM);
        cudaFuncSetAttribute(wo_gemm,
                             cudaFuncAttributeMaxDynamicSharedMemorySize, GEMM_SMEM);
        attr_set = true;
    }

    // fp32 -> fp16 pre-conversion
    cvt_f16<<<1184, 256>>>((const float4*)hs, (uint2*)hsh, SLEN * HIDDEN / 4);
    cvt_f16<<<1184, 256>>>((const float4*)Wq, (uint2*)wqh, QDIM * HIDDEN / 4);
    cvt_f16<<<592, 256>>>((const float4*)Wk, (uint2*)wkh, KVDIM * HIDDEN / 4);
    cvt_f16<<<592, 256>>>((const float4*)Wv, (uint2*)wvh, KVDIM * HIDDEN / 4);
    cvt_f16<<<1184, 256>>>((const float4*)Wo, (uint2*)woh, HIDDEN * QDIM / 4);

    qkv_gemm<<<dim3(40, SLEN / 128), 256, GEMM_SMEM>>>(bq, bk, bv);
    flash_f16<<<dim3(SLEN / 128, NHEADS), 256>>>();
    wo_gemm<<<dim3((HIDDEN + 127) / 128, SLEN / 128), 256, GEMM_SMEM>>>(bo, out);
}